// round 2
// baseline (speedup 1.0000x reference)
#include <cuda_runtime.h>
#include <math.h>

#define NN 100000
#define FIN 512
#define HH 8
#define D1 64
#define C1 8
#define D2 80
#define C2 10

// ---------------- scratch (device globals; no allocation allowed) ----------
__device__ float g_h1[(size_t)NN * D1];
__device__ float g_ss1[NN * HH];
__device__ float g_sd1[NN * HH];
__device__ float g_m1[NN * HH];
__device__ float g_dn1[NN * HH];
__device__ float g_agg1[(size_t)NN * D1];
__device__ float g_hid[(size_t)NN * D1];
__device__ float g_h2[(size_t)NN * D2];
__device__ float g_ss2[NN * HH];
__device__ float g_sd2[NN * HH];
__device__ float g_m2[NN * HH];
__device__ float g_dn2[NN * HH];

// ---------------- helpers ---------------------------------------------------
__device__ __forceinline__ void atomicMaxF(float* a, float v) {
    if (v >= 0.f) atomicMax((int*)a, __float_as_int(v));
    else          atomicMin((unsigned int*)a, __float_as_uint(v));
}

__device__ __forceinline__ float lrelu(float t) { return t > 0.f ? t : 0.2f * t; }

// ---------------- init -------------------------------------------------------
__global__ void k_init(float* __restrict__ dout) {
    int i = blockIdx.x * blockDim.x + threadIdx.x;
    if (i < NN * HH) {
        g_m1[i] = -INFINITY; g_m2[i] = -INFINITY;
        g_dn1[i] = 0.f;      g_dn2[i] = 0.f;
    }
    if (i < NN * D1) g_agg1[i] = 0.f;
    if (i < NN * D2) dout[i] = 0.f;
}

// ---------------- GEMM1: h1 = x @ W1  (M=100000, K=512, N=64) ----------------
__global__ __launch_bounds__(256) void k_gemm1(const float* __restrict__ x,
                                               const float* __restrict__ W) {
    __shared__ float As[32][68];  // [k][m]
    __shared__ float Bs[32][68];  // [k][n]
    const int bm = blockIdx.x * 64;
    const int tid = threadIdx.x;
    const int tx = tid & 15, ty = tid >> 4;
    float acc[4][4] = {};
    for (int k0 = 0; k0 < FIN; k0 += 32) {
        const int ar = tid >> 3, ac = (tid & 7) * 4;
#pragma unroll
        for (int rr = 0; rr < 2; rr++) {
            int row = ar + rr * 32;
            float4 v = make_float4(0.f, 0.f, 0.f, 0.f);
            if (bm + row < NN)
                v = *(const float4*)&x[(size_t)(bm + row) * FIN + k0 + ac];
            As[ac + 0][row] = v.x; As[ac + 1][row] = v.y;
            As[ac + 2][row] = v.z; As[ac + 3][row] = v.w;
        }
        const int br = tid >> 4, bc = (tid & 15) * 4;
#pragma unroll
        for (int rr = 0; rr < 2; rr++) {
            int row = br + rr * 16;
            *(float4*)&Bs[row][bc] = *(const float4*)&W[(size_t)(k0 + row) * 64 + bc];
        }
        __syncthreads();
#pragma unroll
        for (int kc = 0; kc < 32; kc++) {
            float4 a4 = *(const float4*)&As[kc][ty * 4];
            float4 b4 = *(const float4*)&Bs[kc][tx * 4];
            float av[4] = {a4.x, a4.y, a4.z, a4.w};
            float bv[4] = {b4.x, b4.y, b4.z, b4.w};
#pragma unroll
            for (int i = 0; i < 4; i++)
#pragma unroll
                for (int j = 0; j < 4; j++) acc[i][j] += av[i] * bv[j];
        }
        __syncthreads();
    }
#pragma unroll
    for (int i = 0; i < 4; i++) {
        int row = bm + ty * 4 + i;
        if (row < NN) {
#pragma unroll
            for (int j = 0; j < 4; j++)
                g_h1[(size_t)row * 64 + tx * 4 + j] = acc[i][j];
        }
    }
}

// ---------------- GEMM2: h2 = hid @ W2  (M=100000, K=64, N=80) ---------------
__global__ __launch_bounds__(256) void k_gemm2(const float* __restrict__ W) {
    __shared__ float As[64][68];  // [k][m]
    __shared__ float Bs[64][80];  // [k][n]
    const int bm = blockIdx.x * 64;
    const int tid = threadIdx.x;
    const int tx = tid & 15, ty = tid >> 4;
    for (int i = tid; i < 64 * 80; i += 256) Bs[i / 80][i % 80] = W[i];
    const int ar = tid >> 4, ac = (tid & 15) * 4;
#pragma unroll
    for (int rr = 0; rr < 4; rr++) {
        int row = ar + rr * 16;
        float4 v = make_float4(0.f, 0.f, 0.f, 0.f);
        if (bm + row < NN)
            v = *(const float4*)&g_hid[(size_t)(bm + row) * 64 + ac];
        As[ac + 0][row] = v.x; As[ac + 1][row] = v.y;
        As[ac + 2][row] = v.z; As[ac + 3][row] = v.w;
    }
    __syncthreads();
    float acc[4][5] = {};
#pragma unroll 8
    for (int k = 0; k < 64; k++) {
        float4 a4 = *(const float4*)&As[k][ty * 4];
        float av[4] = {a4.x, a4.y, a4.z, a4.w};
        float bv[5];
#pragma unroll
        for (int j = 0; j < 5; j++) bv[j] = Bs[k][tx * 5 + j];
#pragma unroll
        for (int i = 0; i < 4; i++)
#pragma unroll
            for (int j = 0; j < 5; j++) acc[i][j] += av[i] * bv[j];
    }
#pragma unroll
    for (int i = 0; i < 4; i++) {
        int row = bm + ty * 4 + i;
        if (row < NN) {
#pragma unroll
            for (int j = 0; j < 5; j++)
                g_h2[(size_t)row * 80 + tx * 5 + j] = acc[i][j];
        }
    }
}

// ---------------- attention scores s_src/s_dst -------------------------------
__device__ __forceinline__ void calcs_body(const float* __restrict__ h,
                                           const float* __restrict__ asrc,
                                           const float* __restrict__ adst,
                                           float* __restrict__ ss,
                                           float* __restrict__ sd,
                                           int C, int D) {
    int i = blockIdx.x * blockDim.x + threadIdx.x;
    if (i >= NN * HH) return;
    int node = i >> 3, hh = i & 7;
    const float* hp = h + (size_t)node * D + hh * C;
    float a = 0.f, b = 0.f;
    for (int c = 0; c < C; c++) {
        float v = hp[c];
        a += v * asrc[hh * C + c];
        b += v * adst[hh * C + c];
    }
    ss[i] = a; sd[i] = b;
}
__global__ void k_calcs1(const float* __restrict__ as, const float* __restrict__ ad) {
    calcs_body(g_h1, as, ad, g_ss1, g_sd1, C1, D1);
}
__global__ void k_calcs2(const float* __restrict__ as, const float* __restrict__ ad) {
    calcs_body(g_h2, as, ad, g_ss2, g_sd2, C2, D2);
}

// ---------------- edge pass A: segment max -----------------------------------
__device__ __forceinline__ void emax_body(const int* __restrict__ ei, int E, int ET,
                                          const float* __restrict__ ss,
                                          const float* __restrict__ sd,
                                          float* __restrict__ m) {
    int e = blockIdx.x * blockDim.x + threadIdx.x;
    if (e >= ET) return;
    int src, dst;
    if (e < E) { src = ei[e]; dst = ei[(size_t)E + e]; }
    else       { src = dst = e - E; }
    float4 s0 = *(const float4*)(ss + (size_t)src * 8);
    float4 s1 = *(const float4*)(ss + (size_t)src * 8 + 4);
    float4 d0 = *(const float4*)(sd + (size_t)dst * 8);
    float4 d1 = *(const float4*)(sd + (size_t)dst * 8 + 4);
    float ev[8] = {s0.x + d0.x, s0.y + d0.y, s0.z + d0.z, s0.w + d0.w,
                   s1.x + d1.x, s1.y + d1.y, s1.z + d1.z, s1.w + d1.w};
#pragma unroll
    for (int h = 0; h < 8; h++) atomicMaxF(&m[(size_t)dst * 8 + h], lrelu(ev[h]));
}
__global__ void k_emax1(const int* ei, int E, int ET) { emax_body(ei, E, ET, g_ss1, g_sd1, g_m1); }
__global__ void k_emax2(const int* ei, int E, int ET) { emax_body(ei, E, ET, g_ss2, g_sd2, g_m2); }

// ---------------- edge pass B: segment sum of exp ----------------------------
__device__ __forceinline__ void esum_body(const int* __restrict__ ei, int E, int ET,
                                          const float* __restrict__ ss,
                                          const float* __restrict__ sd,
                                          const float* __restrict__ m,
                                          float* __restrict__ dn) {
    int e = blockIdx.x * blockDim.x + threadIdx.x;
    if (e >= ET) return;
    int src, dst;
    if (e < E) { src = ei[e]; dst = ei[(size_t)E + e]; }
    else       { src = dst = e - E; }
    float4 s0 = *(const float4*)(ss + (size_t)src * 8);
    float4 s1 = *(const float4*)(ss + (size_t)src * 8 + 4);
    float4 d0 = *(const float4*)(sd + (size_t)dst * 8);
    float4 d1 = *(const float4*)(sd + (size_t)dst * 8 + 4);
    float4 m0 = *(const float4*)(m + (size_t)dst * 8);
    float4 m1v = *(const float4*)(m + (size_t)dst * 8 + 4);
    float ev[8] = {s0.x + d0.x, s0.y + d0.y, s0.z + d0.z, s0.w + d0.w,
                   s1.x + d1.x, s1.y + d1.y, s1.z + d1.z, s1.w + d1.w};
    float mv[8] = {m0.x, m0.y, m0.z, m0.w, m1v.x, m1v.y, m1v.z, m1v.w};
#pragma unroll
    for (int h = 0; h < 8; h++)
        atomicAdd(&dn[(size_t)dst * 8 + h], expf(lrelu(ev[h]) - mv[h]));
}
__global__ void k_esum1(const int* ei, int E, int ET) { esum_body(ei, E, ET, g_ss1, g_sd1, g_m1, g_dn1); }
__global__ void k_esum2(const int* ei, int E, int ET) { esum_body(ei, E, ET, g_ss2, g_sd2, g_m2, g_dn2); }

// ---------------- edge pass C: weighted aggregation (warp per edge) ----------
template <int D, int C>
__device__ __forceinline__ void eagg_body(const int* __restrict__ ei, int E, int ET,
                                          const float* __restrict__ ss,
                                          const float* __restrict__ sd,
                                          const float* __restrict__ m,
                                          const float* __restrict__ dn,
                                          const float* __restrict__ hb,
                                          float* __restrict__ agg) {
    int w = (blockIdx.x * blockDim.x + threadIdx.x) >> 5;
    int lane = threadIdx.x & 31;
    if (w >= ET) return;
    int src, dst;
    if (w < E) { src = ei[w]; dst = ei[(size_t)E + w]; }
    else       { src = dst = w - E; }
    size_t sb = (size_t)src * 8, db = (size_t)dst * 8;
#pragma unroll
    for (int cc = 0; cc < (D + 31) / 32; cc++) {
        int c = lane + cc * 32;
        if (c < D) {
            int h = c / C;
            float t = lrelu(ss[sb + h] + sd[db + h]);
            float alpha = expf(t - m[db + h]) / (dn[db + h] + 1e-16f);
            atomicAdd(&agg[(size_t)dst * D + c], hb[(size_t)src * D + c] * alpha);
        }
    }
}
__global__ void k_eagg1(const int* ei, int E, int ET) {
    eagg_body<D1, C1>(ei, E, ET, g_ss1, g_sd1, g_m1, g_dn1, g_h1, g_agg1);
}
__global__ void k_eagg2(const int* ei, int E, int ET, float* __restrict__ out) {
    eagg_body<D2, C2>(ei, E, ET, g_ss2, g_sd2, g_m2, g_dn2, g_h2, out);
}

// ---------------- layer-1 epilogue: hid = elu(agg1 + b1) ---------------------
__global__ void k_post1(const float* __restrict__ b1) {
    int i = blockIdx.x * blockDim.x + threadIdx.x;
    if (i >= NN * D1) return;
    float v = g_agg1[i] + b1[i & 63];
    g_hid[i] = v > 0.f ? v : (expf(v) - 1.f);
}

// ---------------- final: out = log_softmax(agg2 + b2) (warp per row) ---------
__global__ void k_final(float* __restrict__ out, const float* __restrict__ b2) {
    int w = (blockIdx.x * blockDim.x + threadIdx.x) >> 5;
    int lane = threadIdx.x & 31;
    if (w >= NN) return;
    float* row = out + (size_t)w * 80;
    float v0 = row[lane] + b2[lane];
    float v1 = row[lane + 32] + b2[lane + 32];
    float v2 = (lane < 16) ? row[lane + 64] + b2[lane + 64] : -INFINITY;
    float mx = fmaxf(fmaxf(v0, v1), v2);
#pragma unroll
    for (int o = 16; o; o >>= 1) mx = fmaxf(mx, __shfl_xor_sync(0xFFFFFFFFu, mx, o));
    float s = expf(v0 - mx) + expf(v1 - mx) + ((lane < 16) ? expf(v2 - mx) : 0.f);
#pragma unroll
    for (int o = 16; o; o >>= 1) s += __shfl_xor_sync(0xFFFFFFFFu, s, o);
    float lse = mx + logf(s);
    row[lane] = v0 - lse;
    row[lane + 32] = v1 - lse;
    if (lane < 16) row[lane + 64] = v2 - lse;
}

// ---------------- launcher ----------------------------------------------------
extern "C" void kernel_launch(void* const* d_in, const int* in_sizes, int n_in,
                              void* d_out, int out_size) {
    const float* x       = (const float*)d_in[0];
    const int*   ei      = (const int*)d_in[1];
    const float* W1      = (const float*)d_in[2];
    const float* as1     = (const float*)d_in[3];
    const float* ad1     = (const float*)d_in[4];
    const float* b1      = (const float*)d_in[5];
    const float* W2      = (const float*)d_in[6];
    const float* as2     = (const float*)d_in[7];
    const float* ad2     = (const float*)d_in[8];
    const float* b2      = (const float*)d_in[9];
    float* out           = (float*)d_out;

    const int E  = in_sizes[1] / 2;
    const int ET = E + NN;

    const int T = 256;
    k_init<<<(NN * D2 + T - 1) / T, T>>>(out);
    k_gemm1<<<(NN + 63) / 64, 256>>>(x, W1);
    k_calcs1<<<(NN * HH + T - 1) / T, T>>>(as1, ad1);
    k_emax1<<<(ET + T - 1) / T, T>>>(ei, E, ET);
    k_esum1<<<(ET + T - 1) / T, T>>>(ei, E, ET);
    {
        long long thr = (long long)ET * 32;
        k_eagg1<<<(unsigned)((thr + T - 1) / T), T>>>(ei, E, ET);
    }
    k_post1<<<(NN * D1 + T - 1) / T, T>>>(b1);
    k_gemm2<<<(NN + 63) / 64, 256>>>(W2);
    k_calcs2<<<(NN * HH + T - 1) / T, T>>>(as2, ad2);
    k_emax2<<<(ET + T - 1) / T, T>>>(ei, E, ET);
    k_esum2<<<(ET + T - 1) / T, T>>>(ei, E, ET);
    {
        long long thr = (long long)ET * 32;
        k_eagg2<<<(unsigned)((thr + T - 1) / T), T>>>(ei, E, ET, out);
    }
    k_final<<<(NN * 32 + T - 1) / T, T>>>(out, b2);
}

// round 4
// speedup vs baseline: 1.4325x; 1.4325x over previous
#include <cuda_runtime.h>
#include <math.h>

#define NN 100000
#define FIN 512
#define HH 8
#define D1 64
#define C1 8
#define D2 80
#define C2 10
#define MAXET 3300000   // E=3.2M + N self loops

// ---------------- scratch (device globals; no allocation allowed) ----------
__device__ float g_h1[(size_t)NN * D1];
__device__ float g_ss1[NN * HH];
__device__ float g_sd1[NN * HH];
__device__ float g_m1[NN * HH];
__device__ float g_dn1[NN * HH];
__device__ float2 g_mi1[NN * HH];
__device__ float g_agg1[(size_t)NN * D1];
__device__ float g_hid[(size_t)NN * D1];
__device__ float g_h2[(size_t)NN * D2];
__device__ float g_ss2[NN * HH];
__device__ float g_sd2[NN * HH];
__device__ float g_m2[NN * HH];
__device__ float g_dn2[NN * HH];
__device__ float2 g_mi2[NN * HH];
__device__ float g_e[(size_t)MAXET * 8];   // per-edge lrelu scores (reused per layer)

// ---------------- helpers ---------------------------------------------------
__device__ __forceinline__ void atomicMaxF(float* a, float v) {
    if (v >= 0.f) atomicMax((int*)a, __float_as_int(v));
    else          atomicMin((unsigned int*)a, __float_as_uint(v));
}
__device__ __forceinline__ float lrelu(float t) { return t > 0.f ? t : 0.2f * t; }
__device__ __forceinline__ void redv4(float* p, float a, float b, float c, float d) {
    asm volatile("red.global.add.v4.f32 [%0], {%1,%2,%3,%4};"
                 :: "l"(p), "f"(a), "f"(b), "f"(c), "f"(d) : "memory");
}

// ---------------- init -------------------------------------------------------
__global__ void k_init(float* __restrict__ dout) {
    int i = blockIdx.x * blockDim.x + threadIdx.x;
    if (i < NN * HH) {
        g_m1[i] = -INFINITY; g_m2[i] = -INFINITY;
        g_dn1[i] = 0.f;      g_dn2[i] = 0.f;
    }
    if (i < NN * D1) g_agg1[i] = 0.f;
    if (i < NN * D2) dout[i] = 0.f;
}

// ---------------- GEMM1: h1 = x @ W1  (M=100000, K=512, N=64) ----------------
// 128x64 tile, 256 threads, 8x4 accum per thread.
__global__ __launch_bounds__(256) void k_gemm1(const float* __restrict__ x,
                                               const float* __restrict__ W) {
    __shared__ float As[16][132];  // [k][m]
    __shared__ float Bs[16][64];   // [k][n]
    const int bm = blockIdx.x * 128;
    const int tid = threadIdx.x;
    const int tx = tid & 15, ty = tid >> 4;
    float acc[8][4] = {};
    for (int k0 = 0; k0 < FIN; k0 += 16) {
#pragma unroll
        for (int i = 0; i < 2; i++) {
            int f = tid * 2 + i;
            int row = f >> 2, kq = (f & 3) * 4;
            float4 v = make_float4(0.f, 0.f, 0.f, 0.f);
            if (bm + row < NN)
                v = *(const float4*)&x[(size_t)(bm + row) * FIN + k0 + kq];
            As[kq + 0][row] = v.x; As[kq + 1][row] = v.y;
            As[kq + 2][row] = v.z; As[kq + 3][row] = v.w;
        }
        {
            int kr = tid >> 4, nc = (tid & 15) * 4;
            *(float4*)&Bs[kr][nc] = *(const float4*)&W[(size_t)(k0 + kr) * 64 + nc];
        }
        __syncthreads();
#pragma unroll
        for (int k = 0; k < 16; k++) {
            float4 a0 = *(const float4*)&As[k][ty * 8];
            float4 a1 = *(const float4*)&As[k][ty * 8 + 4];
            float4 b  = *(const float4*)&Bs[k][tx * 4];
            float av[8] = {a0.x, a0.y, a0.z, a0.w, a1.x, a1.y, a1.z, a1.w};
            float bv[4] = {b.x, b.y, b.z, b.w};
#pragma unroll
            for (int i = 0; i < 8; i++)
#pragma unroll
                for (int j = 0; j < 4; j++) acc[i][j] += av[i] * bv[j];
        }
        __syncthreads();
    }
#pragma unroll
    for (int i = 0; i < 8; i++) {
        int row = bm + ty * 8 + i;
        if (row < NN) {
            float4 v = make_float4(acc[i][0], acc[i][1], acc[i][2], acc[i][3]);
            *(float4*)&g_h1[(size_t)row * 64 + tx * 4] = v;
        }
    }
}

// ---------------- GEMM2: h2 = hid @ W2  (M=100000, K=64, N=80) ---------------
__global__ __launch_bounds__(256) void k_gemm2(const float* __restrict__ W) {
    __shared__ float As[64][68];  // [k][m]
    __shared__ float Bs[64][80];  // [k][n]
    const int bm = blockIdx.x * 64;
    const int tid = threadIdx.x;
    const int tx = tid & 15, ty = tid >> 4;
    for (int i = tid; i < 64 * 80; i += 256) Bs[i / 80][i % 80] = W[i];
    const int ar = tid >> 4, ac = (tid & 15) * 4;
#pragma unroll
    for (int rr = 0; rr < 4; rr++) {
        int row = ar + rr * 16;
        float4 v = make_float4(0.f, 0.f, 0.f, 0.f);
        if (bm + row < NN)
            v = *(const float4*)&g_hid[(size_t)(bm + row) * 64 + ac];
        As[ac + 0][row] = v.x; As[ac + 1][row] = v.y;
        As[ac + 2][row] = v.z; As[ac + 3][row] = v.w;
    }
    __syncthreads();
    float acc[4][5] = {};
#pragma unroll 8
    for (int k = 0; k < 64; k++) {
        float4 a4 = *(const float4*)&As[k][ty * 4];
        float av[4] = {a4.x, a4.y, a4.z, a4.w};
        float bv[5];
#pragma unroll
        for (int j = 0; j < 5; j++) bv[j] = Bs[k][tx * 5 + j];
#pragma unroll
        for (int i = 0; i < 4; i++)
#pragma unroll
            for (int j = 0; j < 5; j++) acc[i][j] += av[i] * bv[j];
    }
#pragma unroll
    for (int i = 0; i < 4; i++) {
        int row = bm + ty * 4 + i;
        if (row < NN) {
#pragma unroll
            for (int j = 0; j < 5; j++)
                g_h2[(size_t)row * 80 + tx * 5 + j] = acc[i][j];
        }
    }
}

// ---------------- attention scores s_src/s_dst -------------------------------
__device__ __forceinline__ void calcs_body(const float* __restrict__ h,
                                           const float* __restrict__ asrc,
                                           const float* __restrict__ adst,
                                           float* __restrict__ ss,
                                           float* __restrict__ sd,
                                           int C, int D) {
    int i = blockIdx.x * blockDim.x + threadIdx.x;
    if (i >= NN * HH) return;
    int node = i >> 3, hh = i & 7;
    const float* hp = h + (size_t)node * D + hh * C;
    float a = 0.f, b = 0.f;
    for (int c = 0; c < C; c++) {
        float v = hp[c];
        a += v * asrc[hh * C + c];
        b += v * adst[hh * C + c];
    }
    ss[i] = a; sd[i] = b;
}
__global__ void k_calcs1(const float* __restrict__ as, const float* __restrict__ ad) {
    calcs_body(g_h1, as, ad, g_ss1, g_sd1, C1, D1);
}
__global__ void k_calcs2(const float* __restrict__ as, const float* __restrict__ ad) {
    calcs_body(g_h2, as, ad, g_ss2, g_sd2, C2, D2);
}

// ---------------- edge pass A: compute e, store, segment max ------------------
__device__ __forceinline__ void emax_body(const int* __restrict__ ei, int E, int ET,
                                          const float* __restrict__ ss,
                                          const float* __restrict__ sd,
                                          float* __restrict__ m) {
    int e = blockIdx.x * blockDim.x + threadIdx.x;
    if (e >= ET) return;
    int src, dst;
    if (e < E) { src = ei[e]; dst = ei[(size_t)E + e]; }
    else       { src = dst = e - E; }
    float4 s0 = *(const float4*)(ss + (size_t)src * 8);
    float4 s1 = *(const float4*)(ss + (size_t)src * 8 + 4);
    float4 d0 = *(const float4*)(sd + (size_t)dst * 8);
    float4 d1 = *(const float4*)(sd + (size_t)dst * 8 + 4);
    float ev[8] = {lrelu(s0.x + d0.x), lrelu(s0.y + d0.y), lrelu(s0.z + d0.z), lrelu(s0.w + d0.w),
                   lrelu(s1.x + d1.x), lrelu(s1.y + d1.y), lrelu(s1.z + d1.z), lrelu(s1.w + d1.w)};
    float4* ep = (float4*)&g_e[(size_t)e * 8];
    asm volatile("st.global.cs.v4.f32 [%0], {%1,%2,%3,%4};" :: "l"(ep),   "f"(ev[0]),"f"(ev[1]),"f"(ev[2]),"f"(ev[3]) : "memory");
    asm volatile("st.global.cs.v4.f32 [%0], {%1,%2,%3,%4};" :: "l"(ep+1), "f"(ev[4]),"f"(ev[5]),"f"(ev[6]),"f"(ev[7]) : "memory");
#pragma unroll
    for (int h = 0; h < 8; h++) atomicMaxF(&m[(size_t)dst * 8 + h], ev[h]);
}
__global__ void k_emax1(const int* ei, int E, int ET) { emax_body(ei, E, ET, g_ss1, g_sd1, g_m1); }
__global__ void k_emax2(const int* ei, int E, int ET) { emax_body(ei, E, ET, g_ss2, g_sd2, g_m2); }

// ---------------- edge pass B: segment sum of exp (vector atomics) -----------
__device__ __forceinline__ void esum_body(const int* __restrict__ ei, int E, int ET,
                                          const float* __restrict__ m,
                                          float* __restrict__ dn) {
    int e = blockIdx.x * blockDim.x + threadIdx.x;
    if (e >= ET) return;
    int dst = (e < E) ? ei[(size_t)E + e] : (e - E);
    const float4* ep = (const float4*)&g_e[(size_t)e * 8];
    float4 e0 = ep[0], e1 = ep[1];
    float4 m0 = *(const float4*)(m + (size_t)dst * 8);
    float4 m1v = *(const float4*)(m + (size_t)dst * 8 + 4);
    redv4(&dn[(size_t)dst * 8],     expf(e0.x - m0.x), expf(e0.y - m0.y), expf(e0.z - m0.z), expf(e0.w - m0.w));
    redv4(&dn[(size_t)dst * 8 + 4], expf(e1.x - m1v.x), expf(e1.y - m1v.y), expf(e1.z - m1v.z), expf(e1.w - m1v.w));
}
__global__ void k_esum1(const int* ei, int E, int ET) { esum_body(ei, E, ET, g_m1, g_dn1); }
__global__ void k_esum2(const int* ei, int E, int ET) { esum_body(ei, E, ET, g_m2, g_dn2); }

// ---------------- prep: interleaved (m, 1/(dn+eps)) — device symbols inside ---
__global__ void k_prep1() {
    int i = blockIdx.x * blockDim.x + threadIdx.x;
    if (i < NN * HH) g_mi1[i] = make_float2(g_m1[i], 1.f / (g_dn1[i] + 1e-16f));
}
__global__ void k_prep2() {
    int i = blockIdx.x * blockDim.x + threadIdx.x;
    if (i < NN * HH) g_mi2[i] = make_float2(g_m2[i], 1.f / (g_dn2[i] + 1e-16f));
}

// ---------------- edge pass C layer1: 16 lanes/edge, float4 red --------------
__global__ void k_eagg1(const int* __restrict__ ei, int E, int ET) {
    int g = blockIdx.x * blockDim.x + threadIdx.x;
    int edge = g >> 4;
    int lane = g & 15;
    if (edge >= ET) return;
    int src, dst;
    if (edge < E) { src = ei[edge]; dst = ei[(size_t)E + edge]; }
    else          { src = dst = edge - E; }
    int c4 = lane * 4;
    int h = lane >> 1;                 // C1=8: float4 fully inside one head
    float ev = g_e[(size_t)edge * 8 + h];
    float2 mi = g_mi1[(size_t)dst * 8 + h];
    float alpha = expf(ev - mi.x) * mi.y;
    float4 hv = *(const float4*)&g_h1[(size_t)src * 64 + c4];
    redv4(&g_agg1[(size_t)dst * 64 + c4], hv.x * alpha, hv.y * alpha, hv.z * alpha, hv.w * alpha);
}

// ---------------- edge pass C layer2: 20 lanes/edge (warp), float4 red -------
__global__ void k_eagg2(const int* __restrict__ ei, int E, int ET, float* __restrict__ out) {
    int w = (blockIdx.x * blockDim.x + threadIdx.x) >> 5;
    int lane = threadIdx.x & 31;
    if (w >= ET || lane >= 20) return;
    int src, dst;
    if (w < E) { src = ei[w]; dst = ei[(size_t)E + w]; }
    else       { src = dst = w - E; }
    int c4 = lane * 4;
    float4 hv = *(const float4*)&g_h2[(size_t)src * 80 + c4];
    float a[4];
#pragma unroll
    for (int j = 0; j < 4; j++) {
        int h = (c4 + j) / 10;
        float ev = g_e[(size_t)w * 8 + h];
        float2 mi = g_mi2[(size_t)dst * 8 + h];
        a[j] = expf(ev - mi.x) * mi.y;
    }
    redv4(&out[(size_t)dst * 80 + c4], hv.x * a[0], hv.y * a[1], hv.z * a[2], hv.w * a[3]);
}

// ---------------- layer-1 epilogue: hid = elu(agg1 + b1) ---------------------
__global__ void k_post1(const float* __restrict__ b1) {
    int i = blockIdx.x * blockDim.x + threadIdx.x;
    if (i >= NN * D1) return;
    float v = g_agg1[i] + b1[i & 63];
    g_hid[i] = v > 0.f ? v : (expf(v) - 1.f);
}

// ---------------- final: out = log_softmax(agg2 + b2) (warp per row) ---------
__global__ void k_final(float* __restrict__ out, const float* __restrict__ b2) {
    int w = (blockIdx.x * blockDim.x + threadIdx.x) >> 5;
    int lane = threadIdx.x & 31;
    if (w >= NN) return;
    float* row = out + (size_t)w * 80;
    float v0 = row[lane] + b2[lane];
    float v1 = row[lane + 32] + b2[lane + 32];
    float v2 = (lane < 16) ? row[lane + 64] + b2[lane + 64] : -INFINITY;
    float mx = fmaxf(fmaxf(v0, v1), v2);
#pragma unroll
    for (int o = 16; o; o >>= 1) mx = fmaxf(mx, __shfl_xor_sync(0xFFFFFFFFu, mx, o));
    float s = expf(v0 - mx) + expf(v1 - mx) + ((lane < 16) ? expf(v2 - mx) : 0.f);
#pragma unroll
    for (int o = 16; o; o >>= 1) s += __shfl_xor_sync(0xFFFFFFFFu, s, o);
    float lse = mx + logf(s);
    row[lane] = v0 - lse;
    row[lane + 32] = v1 - lse;
    if (lane < 16) row[lane + 64] = v2 - lse;
}

// ---------------- launcher ----------------------------------------------------
extern "C" void kernel_launch(void* const* d_in, const int* in_sizes, int n_in,
                              void* d_out, int out_size) {
    const float* x       = (const float*)d_in[0];
    const int*   ei      = (const int*)d_in[1];
    const float* W1      = (const float*)d_in[2];
    const float* as1     = (const float*)d_in[3];
    const float* ad1     = (const float*)d_in[4];
    const float* b1      = (const float*)d_in[5];
    const float* W2      = (const float*)d_in[6];
    const float* as2     = (const float*)d_in[7];
    const float* ad2     = (const float*)d_in[8];
    const float* b2      = (const float*)d_in[9];
    float* out           = (float*)d_out;

    const int E  = in_sizes[1] / 2;
    const int ET = E + NN;

    const int T = 256;
    k_init<<<(NN * D2 + T - 1) / T, T>>>(out);
    k_gemm1<<<(NN + 127) / 128, 256>>>(x, W1);
    k_calcs1<<<(NN * HH + T - 1) / T, T>>>(as1, ad1);
    k_emax1<<<(ET + T - 1) / T, T>>>(ei, E, ET);
    k_esum1<<<(ET + T - 1) / T, T>>>(ei, E, ET);
    k_prep1<<<(NN * HH + T - 1) / T, T>>>();
    {
        long long thr = (long long)ET * 16;
        k_eagg1<<<(unsigned)((thr + T - 1) / T), T>>>(ei, E, ET);
    }
    k_post1<<<(NN * D1 + T - 1) / T, T>>>(b1);
    k_gemm2<<<(NN + 63) / 64, 256>>>(W2);
    k_calcs2<<<(NN * HH + T - 1) / T, T>>>(as2, ad2);
    k_emax2<<<(ET + T - 1) / T, T>>>(ei, E, ET);
    k_esum2<<<(ET + T - 1) / T, T>>>(ei, E, ET);
    k_prep2<<<(NN * HH + T - 1) / T, T>>>();
    {
        long long thr = (long long)ET * 32;
        k_eagg2<<<(unsigned)((thr + T - 1) / T), T>>>(ei, E, ET, out);
    }
    k_final<<<(NN * 32 + T - 1) / T, T>>>(out, b2);
}

// round 5
// speedup vs baseline: 1.7731x; 1.2378x over previous
#include <cuda_runtime.h>
#include <math.h>

#define NN 100000
#define FIN 512
#define HH 8
#define D1 64
#define C1 8
#define D2 80
#define C2 10
#define MAXET 3300000   // E=3.2M + N self loops

// ---------------- scratch (device globals; no allocation allowed) ----------
__device__ float g_h1[(size_t)NN * D1];
__device__ float g_ss1[NN * HH];
__device__ float g_sd1[NN * HH];
__device__ float g_dn1[NN * HH];
__device__ float g_inv1[NN * HH];
__device__ float g_agg1[(size_t)NN * D1];
__device__ float g_hid[(size_t)NN * D1];
__device__ float g_h2[(size_t)NN * D2];
__device__ float g_ss2[NN * HH];
__device__ float g_sd2[NN * HH];
__device__ float g_dn2[NN * HH];
__device__ float g_inv2[NN * HH];
__device__ float g_Ms[16];                 // [0..7] layer1 per-head max(s_src), [8..15] layer2
__device__ float g_e[(size_t)MAXET * 8];   // per-edge exp(e - mb) (reused per layer)

// ---------------- helpers ---------------------------------------------------
__device__ __forceinline__ void atomicMaxF(float* a, float v) {
    if (v >= 0.f) atomicMax((int*)a, __float_as_int(v));
    else          atomicMin((unsigned int*)a, __float_as_uint(v));
}
__device__ __forceinline__ float lrelu(float t) { return t > 0.f ? t : 0.2f * t; }
__device__ __forceinline__ void redv4(float* p, float a, float b, float c, float d) {
    asm volatile("red.global.add.v4.f32 [%0], {%1,%2,%3,%4};"
                 :: "l"(p), "f"(a), "f"(b), "f"(c), "f"(d) : "memory");
}

// ---------------- init -------------------------------------------------------
__global__ void k_init(float* __restrict__ dout) {
    int i = blockIdx.x * blockDim.x + threadIdx.x;
    if (i < 16) g_Ms[i] = -INFINITY;
    if (i < NN * HH) { g_dn1[i] = 0.f; g_dn2[i] = 0.f; }
    if (i < NN * D1) g_agg1[i] = 0.f;
    if (i < NN * D2) dout[i] = 0.f;
}

// ---------------- GEMM1: h1 = x @ W1  (M=100000, K=512, N=64) ----------------
__global__ __launch_bounds__(256) void k_gemm1(const float* __restrict__ x,
                                               const float* __restrict__ W) {
    __shared__ float As[16][132];  // [k][m]
    __shared__ float Bs[16][64];   // [k][n]
    const int bm = blockIdx.x * 128;
    const int tid = threadIdx.x;
    const int tx = tid & 15, ty = tid >> 4;
    float acc[8][4] = {};
    for (int k0 = 0; k0 < FIN; k0 += 16) {
#pragma unroll
        for (int i = 0; i < 2; i++) {
            int f = tid * 2 + i;
            int row = f >> 2, kq = (f & 3) * 4;
            float4 v = make_float4(0.f, 0.f, 0.f, 0.f);
            if (bm + row < NN)
                v = *(const float4*)&x[(size_t)(bm + row) * FIN + k0 + kq];
            As[kq + 0][row] = v.x; As[kq + 1][row] = v.y;
            As[kq + 2][row] = v.z; As[kq + 3][row] = v.w;
        }
        {
            int kr = tid >> 4, nc = (tid & 15) * 4;
            *(float4*)&Bs[kr][nc] = *(const float4*)&W[(size_t)(k0 + kr) * 64 + nc];
        }
        __syncthreads();
#pragma unroll
        for (int k = 0; k < 16; k++) {
            float4 a0 = *(const float4*)&As[k][ty * 8];
            float4 a1 = *(const float4*)&As[k][ty * 8 + 4];
            float4 b  = *(const float4*)&Bs[k][tx * 4];
            float av[8] = {a0.x, a0.y, a0.z, a0.w, a1.x, a1.y, a1.z, a1.w};
            float bv[4] = {b.x, b.y, b.z, b.w};
#pragma unroll
            for (int i = 0; i < 8; i++)
#pragma unroll
                for (int j = 0; j < 4; j++) acc[i][j] += av[i] * bv[j];
        }
        __syncthreads();
    }
#pragma unroll
    for (int i = 0; i < 8; i++) {
        int row = bm + ty * 8 + i;
        if (row < NN) {
            float4 v = make_float4(acc[i][0], acc[i][1], acc[i][2], acc[i][3]);
            *(float4*)&g_h1[(size_t)row * 64 + tx * 4] = v;
        }
    }
}

// ---------------- GEMM2: h2 = hid @ W2  (M=100000, K=64, N=80) ---------------
__global__ __launch_bounds__(256) void k_gemm2(const float* __restrict__ W) {
    __shared__ float As[64][68];
    __shared__ float Bs[64][80];
    const int bm = blockIdx.x * 64;
    const int tid = threadIdx.x;
    const int tx = tid & 15, ty = tid >> 4;
    for (int i = tid; i < 64 * 80; i += 256) Bs[i / 80][i % 80] = W[i];
    const int ar = tid >> 4, ac = (tid & 15) * 4;
#pragma unroll
    for (int rr = 0; rr < 4; rr++) {
        int row = ar + rr * 16;
        float4 v = make_float4(0.f, 0.f, 0.f, 0.f);
        if (bm + row < NN)
            v = *(const float4*)&g_hid[(size_t)(bm + row) * 64 + ac];
        As[ac + 0][row] = v.x; As[ac + 1][row] = v.y;
        As[ac + 2][row] = v.z; As[ac + 3][row] = v.w;
    }
    __syncthreads();
    float acc[4][5] = {};
#pragma unroll 8
    for (int k = 0; k < 64; k++) {
        float4 a4 = *(const float4*)&As[k][ty * 4];
        float av[4] = {a4.x, a4.y, a4.z, a4.w};
        float bv[5];
#pragma unroll
        for (int j = 0; j < 5; j++) bv[j] = Bs[k][tx * 5 + j];
#pragma unroll
        for (int i = 0; i < 4; i++)
#pragma unroll
            for (int j = 0; j < 5; j++) acc[i][j] += av[i] * bv[j];
    }
#pragma unroll
    for (int i = 0; i < 4; i++) {
        int row = bm + ty * 4 + i;
        if (row < NN) {
#pragma unroll
            for (int j = 0; j < 5; j++)
                g_h2[(size_t)row * 80 + tx * 5 + j] = acc[i][j];
        }
    }
}

// ---------------- attention scores + per-head global max of s_src ------------
__device__ __forceinline__ void calcs_body(const float* __restrict__ h,
                                           const float* __restrict__ asrc,
                                           const float* __restrict__ adst,
                                           float* __restrict__ ss,
                                           float* __restrict__ sd,
                                           float* __restrict__ Ms,
                                           int C, int D) {
    __shared__ float red[8][9];
    int i = blockIdx.x * blockDim.x + threadIdx.x;
    int node = i >> 3, hh = i & 7;
    float a = -INFINITY, b = 0.f;
    if (i < NN * HH) {
        const float* hp = h + (size_t)node * D + hh * C;
        a = 0.f;
        for (int c = 0; c < C; c++) {
            float v = hp[c];
            a += v * asrc[hh * C + c];
            b += v * adst[hh * C + c];
        }
        ss[i] = a; sd[i] = b;
    }
    // block-reduce max of a per head (lanes with same h are 8 apart)
    float mx = a;
    mx = fmaxf(mx, __shfl_xor_sync(0xFFFFFFFFu, mx, 8));
    mx = fmaxf(mx, __shfl_xor_sync(0xFFFFFFFFu, mx, 16));
    int warp = threadIdx.x >> 5, lane = threadIdx.x & 31;
    if (lane < 8) red[warp][lane] = mx;
    __syncthreads();
    if (warp == 0) {
        float v = red[lane & 7][0];
#pragma unroll
        for (int w = 1; w < 8; w++) v = fmaxf(v, red[lane & 7][w]);
        if (lane < 8) atomicMaxF(&Ms[lane], v);
    }
}
__global__ void k_calcs1(const float* __restrict__ as, const float* __restrict__ ad) {
    calcs_body(g_h1, as, ad, g_ss1, g_sd1, &g_Ms[0], C1, D1);
}
__global__ void k_calcs2(const float* __restrict__ as, const float* __restrict__ ad) {
    calcs_body(g_h2, as, ad, g_ss2, g_sd2, &g_Ms[8], C2, D2);
}

// ------- fused edge pass: e = lrelu(ss+sd); ex = exp(e - mb); store; sum -----
// mb[dst,h] = lrelu(Ms[h] + sd[dst,h]) >= e for every incoming edge (monotone)
__device__ __forceinline__ void escore_body(const int* __restrict__ ei, int E, int ET,
                                            const float* __restrict__ ss,
                                            const float* __restrict__ sd,
                                            const float* __restrict__ Ms,
                                            float* __restrict__ dn) {
    int e = blockIdx.x * blockDim.x + threadIdx.x;
    if (e >= ET) return;
    int src, dst;
    if (e < E) { src = ei[e]; dst = ei[(size_t)E + e]; }
    else       { src = dst = e - E; }
    float4 s0 = *(const float4*)(ss + (size_t)src * 8);
    float4 s1 = *(const float4*)(ss + (size_t)src * 8 + 4);
    float4 d0 = *(const float4*)(sd + (size_t)dst * 8);
    float4 d1 = *(const float4*)(sd + (size_t)dst * 8 + 4);
    float sv[8] = {s0.x, s0.y, s0.z, s0.w, s1.x, s1.y, s1.z, s1.w};
    float dv[8] = {d0.x, d0.y, d0.z, d0.w, d1.x, d1.y, d1.z, d1.w};
    float ex[8];
#pragma unroll
    for (int h = 0; h < 8; h++) {
        float mb = lrelu(__ldg(&Ms[h]) + dv[h]);
        ex[h] = expf(lrelu(sv[h] + dv[h]) - mb);
    }
    float4* ep = (float4*)&g_e[(size_t)e * 8];
    asm volatile("st.global.cs.v4.f32 [%0], {%1,%2,%3,%4};" :: "l"(ep),   "f"(ex[0]),"f"(ex[1]),"f"(ex[2]),"f"(ex[3]) : "memory");
    asm volatile("st.global.cs.v4.f32 [%0], {%1,%2,%3,%4};" :: "l"(ep+1), "f"(ex[4]),"f"(ex[5]),"f"(ex[6]),"f"(ex[7]) : "memory");
    redv4(&dn[(size_t)dst * 8],     ex[0], ex[1], ex[2], ex[3]);
    redv4(&dn[(size_t)dst * 8 + 4], ex[4], ex[5], ex[6], ex[7]);
}
__global__ void k_escore1(const int* ei, int E, int ET) { escore_body(ei, E, ET, g_ss1, g_sd1, &g_Ms[0], g_dn1); }
__global__ void k_escore2(const int* ei, int E, int ET) { escore_body(ei, E, ET, g_ss2, g_sd2, &g_Ms[8], g_dn2); }

// ---------------- prep: inv = 1/dn (dn > 0; self-loop guarantees) ------------
__global__ void k_prep1() {
    int i = blockIdx.x * blockDim.x + threadIdx.x;
    if (i < NN * HH) g_inv1[i] = 1.f / fmaxf(g_dn1[i], 1e-35f);
}
__global__ void k_prep2() {
    int i = blockIdx.x * blockDim.x + threadIdx.x;
    if (i < NN * HH) g_inv2[i] = 1.f / fmaxf(g_dn2[i], 1e-35f);
}

// ---------------- edge pass C layer1: 16 lanes/edge, float4 red --------------
__global__ void k_eagg1(const int* __restrict__ ei, int E, int ET) {
    int g = blockIdx.x * blockDim.x + threadIdx.x;
    int edge = g >> 4;
    int lane = g & 15;
    if (edge >= ET) return;
    int src, dst;
    if (edge < E) { src = ei[edge]; dst = ei[(size_t)E + edge]; }
    else          { src = dst = edge - E; }
    int c4 = lane * 4;
    int h = lane >> 1;                 // C1=8: float4 fully inside one head
    float alpha = g_e[(size_t)edge * 8 + h] * g_inv1[(size_t)dst * 8 + h];
    float4 hv = *(const float4*)&g_h1[(size_t)src * 64 + c4];
    redv4(&g_agg1[(size_t)dst * 64 + c4], hv.x * alpha, hv.y * alpha, hv.z * alpha, hv.w * alpha);
}

// ---------------- edge pass C layer2: 20 lanes/edge (warp), float4 red -------
__global__ void k_eagg2(const int* __restrict__ ei, int E, int ET, float* __restrict__ out) {
    int w = (blockIdx.x * blockDim.x + threadIdx.x) >> 5;
    int lane = threadIdx.x & 31;
    if (w >= ET || lane >= 20) return;
    int src, dst;
    if (w < E) { src = ei[w]; dst = ei[(size_t)E + w]; }
    else       { src = dst = w - E; }
    int c4 = lane * 4;
    float4 hv = *(const float4*)&g_h2[(size_t)src * 80 + c4];
    float a[4];
#pragma unroll
    for (int j = 0; j < 4; j++) {
        int h = (c4 + j) / 10;
        a[j] = g_e[(size_t)w * 8 + h] * g_inv2[(size_t)dst * 8 + h];
    }
    redv4(&out[(size_t)dst * 80 + c4], hv.x * a[0], hv.y * a[1], hv.z * a[2], hv.w * a[3]);
}

// ---------------- layer-1 epilogue: hid = elu(agg1 + b1) ---------------------
__global__ void k_post1(const float* __restrict__ b1) {
    int i = blockIdx.x * blockDim.x + threadIdx.x;
    if (i >= NN * D1) return;
    float v = g_agg1[i] + b1[i & 63];
    g_hid[i] = v > 0.f ? v : (expf(v) - 1.f);
}

// ---------------- final: out = log_softmax(agg2 + b2) (warp per row) ---------
__global__ void k_final(float* __restrict__ out, const float* __restrict__ b2) {
    int w = (blockIdx.x * blockDim.x + threadIdx.x) >> 5;
    int lane = threadIdx.x & 31;
    if (w >= NN) return;
    float* row = out + (size_t)w * 80;
    float v0 = row[lane] + b2[lane];
    float v1 = row[lane + 32] + b2[lane + 32];
    float v2 = (lane < 16) ? row[lane + 64] + b2[lane + 64] : -INFINITY;
    float mx = fmaxf(fmaxf(v0, v1), v2);
#pragma unroll
    for (int o = 16; o; o >>= 1) mx = fmaxf(mx, __shfl_xor_sync(0xFFFFFFFFu, mx, o));
    float s = expf(v0 - mx) + expf(v1 - mx) + ((lane < 16) ? expf(v2 - mx) : 0.f);
#pragma unroll
    for (int o = 16; o; o >>= 1) s += __shfl_xor_sync(0xFFFFFFFFu, s, o);
    float lse = mx + logf(s);
    row[lane] = v0 - lse;
    row[lane + 32] = v1 - lse;
    if (lane < 16) row[lane + 64] = v2 - lse;
}

// ---------------- launcher ----------------------------------------------------
extern "C" void kernel_launch(void* const* d_in, const int* in_sizes, int n_in,
                              void* d_out, int out_size) {
    const float* x       = (const float*)d_in[0];
    const int*   ei      = (const int*)d_in[1];
    const float* W1      = (const float*)d_in[2];
    const float* as1     = (const float*)d_in[3];
    const float* ad1     = (const float*)d_in[4];
    const float* b1      = (const float*)d_in[5];
    const float* W2      = (const float*)d_in[6];
    const float* as2     = (const float*)d_in[7];
    const float* ad2     = (const float*)d_in[8];
    const float* b2      = (const float*)d_in[9];
    float* out           = (float*)d_out;

    const int E  = in_sizes[1] / 2;
    const int ET = E + NN;

    const int T = 256;
    k_init<<<(NN * D2 + T - 1) / T, T>>>(out);
    k_gemm1<<<(NN + 127) / 128, 256>>>(x, W1);
    k_calcs1<<<(NN * HH + T - 1) / T, T>>>(as1, ad1);
    k_escore1<<<(ET + T - 1) / T, T>>>(ei, E, ET);
    k_prep1<<<(NN * HH + T - 1) / T, T>>>();
    {
        long long thr = (long long)ET * 16;
        k_eagg1<<<(unsigned)((thr + T - 1) / T), T>>>(ei, E, ET);
    }
    k_post1<<<(NN * D1 + T - 1) / T, T>>>(b1);
    k_gemm2<<<(NN + 63) / 64, 256>>>(W2);
    k_calcs2<<<(NN * HH + T - 1) / T, T>>>(as2, ad2);
    k_escore2<<<(ET + T - 1) / T, T>>>(ei, E, ET);
    k_prep2<<<(NN * HH + T - 1) / T, T>>>();
    {
        long long thr = (long long)ET * 32;
        k_eagg2<<<(unsigned)((thr + T - 1) / T), T>>>(ei, E, ET, out);
    }
    k_final<<<(NN * 32 + T - 1) / T, T>>>(out, b2);
}

// round 6
// speedup vs baseline: 2.2998x; 1.2971x over previous
#include <cuda_runtime.h>
#include <math.h>

#define NN 100000
#define FIN 512
#define HH 8
#define D1 64
#define C1 8
#define D2 80
#define C2 10
#define MAXET 3300000   // E=3.2M + N self loops

// ---------------- scratch (device globals; no allocation allowed) ----------
__device__ float g_h1[(size_t)NN * D1];
__device__ float g_ss1[NN * HH];
__device__ float g_sd1[NN * HH];
__device__ float g_hid[(size_t)NN * D1];
__device__ float g_h2[(size_t)NN * D2];
__device__ float g_ss2[NN * HH];
__device__ float g_sd2[NN * HH];
__device__ float g_Ms[16];          // [0..7] layer1 per-head max(s_src), [8..15] layer2
__device__ int   g_deg[NN];
__device__ int   g_off[NN];
__device__ int   g_cur[NN];
__device__ int   g_csrc[MAXET];     // src ids bucketed by dst

// ---------------- helpers ---------------------------------------------------
__device__ __forceinline__ void atomicMaxF(float* a, float v) {
    if (v >= 0.f) atomicMax((int*)a, __float_as_int(v));
    else          atomicMin((unsigned int*)a, __float_as_uint(v));
}
__device__ __forceinline__ float lrelu(float t) { return t > 0.f ? t : 0.2f * t; }

// ---------------- CSR build ---------------------------------------------------
__global__ void k_zero() {
    int i = blockIdx.x * blockDim.x + threadIdx.x;
    if (i < NN) g_deg[i] = 0;
    if (i < 16) g_Ms[i] = -INFINITY;
}
__global__ void k_hist(const int* __restrict__ ei, int E, int ET) {
    int e = blockIdx.x * blockDim.x + threadIdx.x;
    if (e >= ET) return;
    int dst = (e < E) ? ei[(size_t)E + e] : (e - E);
    atomicAdd(&g_deg[dst], 1);
}
#define SCAN_T 1024
__global__ __launch_bounds__(SCAN_T) void k_scan() {
    __shared__ int sh[SCAN_T];
    __shared__ int carry_s;
    int tid = threadIdx.x;
    if (tid == 0) carry_s = 0;
    __syncthreads();
    const int CH = (NN + SCAN_T * 4 - 1) / (SCAN_T * 4);
    for (int c = 0; c < CH; c++) {
        int base = c * SCAN_T * 4 + tid * 4;
        int v0 = (base + 0 < NN) ? g_deg[base + 0] : 0;
        int v1 = (base + 1 < NN) ? g_deg[base + 1] : 0;
        int v2 = (base + 2 < NN) ? g_deg[base + 2] : 0;
        int v3 = (base + 3 < NN) ? g_deg[base + 3] : 0;
        int s1 = v0 + v1, s2 = s1 + v2, s3 = s2 + v3;
        sh[tid] = s3;
        __syncthreads();
        for (int o = 1; o < SCAN_T; o <<= 1) {
            int t = (tid >= o) ? sh[tid - o] : 0;
            __syncthreads();
            sh[tid] += t;
            __syncthreads();
        }
        int carry = carry_s;
        int excl = carry + sh[tid] - s3;
        if (base + 0 < NN) { g_off[base + 0] = excl;      g_cur[base + 0] = excl; }
        if (base + 1 < NN) { g_off[base + 1] = excl + v0; g_cur[base + 1] = excl + v0; }
        if (base + 2 < NN) { g_off[base + 2] = excl + s1; g_cur[base + 2] = excl + s1; }
        if (base + 3 < NN) { g_off[base + 3] = excl + s2; g_cur[base + 3] = excl + s2; }
        __syncthreads();
        if (tid == SCAN_T - 1) carry_s = carry + sh[tid];
        __syncthreads();
    }
}
__global__ void k_scatter(const int* __restrict__ ei, int E, int ET) {
    int e = blockIdx.x * blockDim.x + threadIdx.x;
    if (e >= ET) return;
    int src, dst;
    if (e < E) { src = ei[e]; dst = ei[(size_t)E + e]; }
    else       { src = dst = e - E; }
    int pos = atomicAdd(&g_cur[dst], 1);
    g_csrc[pos] = src;
}

// ---------------- GEMM1: h1 = x @ W1  (M=100000, K=512, N=64) ----------------
__global__ __launch_bounds__(256) void k_gemm1(const float* __restrict__ x,
                                               const float* __restrict__ W) {
    __shared__ float As[16][132];
    __shared__ float Bs[16][64];
    const int bm = blockIdx.x * 128;
    const int tid = threadIdx.x;
    const int tx = tid & 15, ty = tid >> 4;
    float acc[8][4] = {};
    for (int k0 = 0; k0 < FIN; k0 += 16) {
#pragma unroll
        for (int i = 0; i < 2; i++) {
            int f = tid * 2 + i;
            int row = f >> 2, kq = (f & 3) * 4;
            float4 v = make_float4(0.f, 0.f, 0.f, 0.f);
            if (bm + row < NN)
                v = *(const float4*)&x[(size_t)(bm + row) * FIN + k0 + kq];
            As[kq + 0][row] = v.x; As[kq + 1][row] = v.y;
            As[kq + 2][row] = v.z; As[kq + 3][row] = v.w;
        }
        {
            int kr = tid >> 4, nc = (tid & 15) * 4;
            *(float4*)&Bs[kr][nc] = *(const float4*)&W[(size_t)(k0 + kr) * 64 + nc];
        }
        __syncthreads();
#pragma unroll
        for (int k = 0; k < 16; k++) {
            float4 a0 = *(const float4*)&As[k][ty * 8];
            float4 a1 = *(const float4*)&As[k][ty * 8 + 4];
            float4 b  = *(const float4*)&Bs[k][tx * 4];
            float av[8] = {a0.x, a0.y, a0.z, a0.w, a1.x, a1.y, a1.z, a1.w};
            float bv[4] = {b.x, b.y, b.z, b.w};
#pragma unroll
            for (int i = 0; i < 8; i++)
#pragma unroll
                for (int j = 0; j < 4; j++) acc[i][j] += av[i] * bv[j];
        }
        __syncthreads();
    }
#pragma unroll
    for (int i = 0; i < 8; i++) {
        int row = bm + ty * 8 + i;
        if (row < NN) {
            float4 v = make_float4(acc[i][0], acc[i][1], acc[i][2], acc[i][3]);
            *(float4*)&g_h1[(size_t)row * 64 + tx * 4] = v;
        }
    }
}

// ---------------- GEMM2: h2 = hid @ W2  (M=100000, K=64, N=80) ---------------
__global__ __launch_bounds__(256) void k_gemm2(const float* __restrict__ W) {
    __shared__ float As[64][68];
    __shared__ float Bs[64][80];
    const int bm = blockIdx.x * 64;
    const int tid = threadIdx.x;
    const int tx = tid & 15, ty = tid >> 4;
    for (int i = tid; i < 64 * 80; i += 256) Bs[i / 80][i % 80] = W[i];
    const int ar = tid >> 4, ac = (tid & 15) * 4;
#pragma unroll
    for (int rr = 0; rr < 4; rr++) {
        int row = ar + rr * 16;
        float4 v = make_float4(0.f, 0.f, 0.f, 0.f);
        if (bm + row < NN)
            v = *(const float4*)&g_hid[(size_t)(bm + row) * 64 + ac];
        As[ac + 0][row] = v.x; As[ac + 1][row] = v.y;
        As[ac + 2][row] = v.z; As[ac + 3][row] = v.w;
    }
    __syncthreads();
    float acc[4][5] = {};
#pragma unroll 8
    for (int k = 0; k < 64; k++) {
        float4 a4 = *(const float4*)&As[k][ty * 4];
        float av[4] = {a4.x, a4.y, a4.z, a4.w};
        float bv[5];
#pragma unroll
        for (int j = 0; j < 5; j++) bv[j] = Bs[k][tx * 5 + j];
#pragma unroll
        for (int i = 0; i < 4; i++)
#pragma unroll
            for (int j = 0; j < 5; j++) acc[i][j] += av[i] * bv[j];
    }
#pragma unroll
    for (int i = 0; i < 4; i++) {
        int row = bm + ty * 4 + i;
        if (row < NN) {
#pragma unroll
            for (int j = 0; j < 5; j++)
                g_h2[(size_t)row * 80 + tx * 5 + j] = acc[i][j];
        }
    }
}

// ---------------- attention scores + per-head global max of s_src ------------
__device__ __forceinline__ void calcs_body(const float* __restrict__ h,
                                           const float* __restrict__ asrc,
                                           const float* __restrict__ adst,
                                           float* __restrict__ ss,
                                           float* __restrict__ sd,
                                           float* __restrict__ Ms,
                                           int C, int D) {
    __shared__ float red[8][9];
    int i = blockIdx.x * blockDim.x + threadIdx.x;
    int node = i >> 3, hh = i & 7;
    float a = -INFINITY, b = 0.f;
    if (i < NN * HH) {
        const float* hp = h + (size_t)node * D + hh * C;
        a = 0.f;
        for (int c = 0; c < C; c++) {
            float v = hp[c];
            a += v * asrc[hh * C + c];
            b += v * adst[hh * C + c];
        }
        ss[i] = a; sd[i] = b;
    }
    float mx = a;
    mx = fmaxf(mx, __shfl_xor_sync(0xFFFFFFFFu, mx, 8));
    mx = fmaxf(mx, __shfl_xor_sync(0xFFFFFFFFu, mx, 16));
    int warp = threadIdx.x >> 5, lane = threadIdx.x & 31;
    if (lane < 8) red[warp][lane] = mx;
    __syncthreads();
    if (warp == 0) {
        float v = red[lane & 7][0];
#pragma unroll
        for (int w = 1; w < 8; w++) v = fmaxf(v, red[lane & 7][w]);
        if (lane < 8) atomicMaxF(&Ms[lane], v);
    }
}
__global__ void k_calcs1(const float* __restrict__ as, const float* __restrict__ ad) {
    calcs_body(g_h1, as, ad, g_ss1, g_sd1, &g_Ms[0], C1, D1);
}
__global__ void k_calcs2(const float* __restrict__ as, const float* __restrict__ ad) {
    calcs_body(g_h2, as, ad, g_ss2, g_sd2, &g_Ms[8], C2, D2);
}

// ---------------- fused GAT layer 1: warp per dst, single edge sweep ---------
__global__ __launch_bounds__(256) void k_gat1(const float* __restrict__ b1) {
    __shared__ int   s_src[8][32];
    __shared__ float s_ex[8][32][8];
    int w = threadIdx.x >> 5, lane = threadIdx.x & 31;
    int dst = blockIdx.x * 8 + w;
    if (dst >= NN) return;
    int off = g_off[dst], deg = g_deg[dst];
    float sdv[8], mb[8];
    {
        float4 t0 = *(const float4*)&g_sd1[(size_t)dst * 8];
        float4 t1 = *(const float4*)&g_sd1[(size_t)dst * 8 + 4];
        sdv[0]=t0.x; sdv[1]=t0.y; sdv[2]=t0.z; sdv[3]=t0.w;
        sdv[4]=t1.x; sdv[5]=t1.y; sdv[6]=t1.z; sdv[7]=t1.w;
#pragma unroll
        for (int h = 0; h < 8; h++) mb[h] = lrelu(__ldg(&g_Ms[h]) + sdv[h]);
    }
    float dn[8] = {0,0,0,0,0,0,0,0};
    float4 acc = make_float4(0.f, 0.f, 0.f, 0.f);
    const int hl = lane >> 1;   // head for channel group lane*4 (lane<16)
    for (int t = 0; t < deg; t += 32) {
        int j = t + lane;
        if (j < deg) {
            int src = g_csrc[off + j];
            s_src[w][lane] = src;
            float4 a0 = *(const float4*)&g_ss1[(size_t)src * 8];
            float4 a1 = *(const float4*)&g_ss1[(size_t)src * 8 + 4];
            float sv[8] = {a0.x, a0.y, a0.z, a0.w, a1.x, a1.y, a1.z, a1.w};
#pragma unroll
            for (int h = 0; h < 8; h++) {
                float ex = expf(lrelu(sv[h] + sdv[h]) - mb[h]);
                dn[h] += ex;
                s_ex[w][lane][h] = ex;
            }
        }
        __syncwarp();
        int cnt = min(32, deg - t);
        for (int jj = 0; jj < cnt; jj++) {
            int src = s_src[w][jj];
            if (lane < 16) {
                float4 hv = *(const float4*)&g_h1[(size_t)src * 64 + lane * 4];
                float ex = s_ex[w][jj][hl];
                acc.x += hv.x * ex; acc.y += hv.y * ex;
                acc.z += hv.z * ex; acc.w += hv.w * ex;
            }
        }
        __syncwarp();
    }
#pragma unroll
    for (int h = 0; h < 8; h++)
#pragma unroll
        for (int o = 16; o; o >>= 1) dn[h] += __shfl_xor_sync(0xFFFFFFFFu, dn[h], o);
    if (lane < 16) {
        float inv = 1.f / fmaxf(dn[hl], 1e-35f);
        float4 bv = *(const float4*)&b1[lane * 4];
        float v[4] = {acc.x * inv + bv.x, acc.y * inv + bv.y,
                      acc.z * inv + bv.z, acc.w * inv + bv.w};
#pragma unroll
        for (int k = 0; k < 4; k++) v[k] = v[k] > 0.f ? v[k] : (expf(v[k]) - 1.f);
        *(float4*)&g_hid[(size_t)dst * 64 + lane * 4] = make_float4(v[0], v[1], v[2], v[3]);
    }
}

// ---------------- fused GAT layer 2 + log_softmax: warp per dst --------------
__global__ __launch_bounds__(256) void k_gat2(const float* __restrict__ b2,
                                              float* __restrict__ out) {
    __shared__ int   s_src[8][32];
    __shared__ float s_ex[8][32][8];
    int w = threadIdx.x >> 5, lane = threadIdx.x & 31;
    int dst = blockIdx.x * 8 + w;
    if (dst >= NN) return;
    int off = g_off[dst], deg = g_deg[dst];
    float sdv[8], mb[8];
    {
        float4 t0 = *(const float4*)&g_sd2[(size_t)dst * 8];
        float4 t1 = *(const float4*)&g_sd2[(size_t)dst * 8 + 4];
        sdv[0]=t0.x; sdv[1]=t0.y; sdv[2]=t0.z; sdv[3]=t0.w;
        sdv[4]=t1.x; sdv[5]=t1.y; sdv[6]=t1.z; sdv[7]=t1.w;
#pragma unroll
        for (int h = 0; h < 8; h++) mb[h] = lrelu(__ldg(&g_Ms[8 + h]) + sdv[h]);
    }
    float dn[8] = {0,0,0,0,0,0,0,0};
    float acc[4] = {0.f, 0.f, 0.f, 0.f};
    const int c0 = lane * 4;
    int hk[4];
#pragma unroll
    for (int k = 0; k < 4; k++) hk[k] = (c0 + k) / 10;   // head per channel (lane<20)
    for (int t = 0; t < deg; t += 32) {
        int j = t + lane;
        if (j < deg) {
            int src = g_csrc[off + j];
            s_src[w][lane] = src;
            float4 a0 = *(const float4*)&g_ss2[(size_t)src * 8];
            float4 a1 = *(const float4*)&g_ss2[(size_t)src * 8 + 4];
            float sv[8] = {a0.x, a0.y, a0.z, a0.w, a1.x, a1.y, a1.z, a1.w};
#pragma unroll
            for (int h = 0; h < 8; h++) {
                float ex = expf(lrelu(sv[h] + sdv[h]) - mb[h]);
                dn[h] += ex;
                s_ex[w][lane][h] = ex;
            }
        }
        __syncwarp();
        int cnt = min(32, deg - t);
        for (int jj = 0; jj < cnt; jj++) {
            int src = s_src[w][jj];
            if (lane < 20) {
                float4 hv = *(const float4*)&g_h2[(size_t)src * 80 + c0];
                acc[0] += hv.x * s_ex[w][jj][hk[0]];
                acc[1] += hv.y * s_ex[w][jj][hk[1]];
                acc[2] += hv.z * s_ex[w][jj][hk[2]];
                acc[3] += hv.w * s_ex[w][jj][hk[3]];
            }
        }
        __syncwarp();
    }
#pragma unroll
    for (int h = 0; h < 8; h++)
#pragma unroll
        for (int o = 16; o; o >>= 1) dn[h] += __shfl_xor_sync(0xFFFFFFFFu, dn[h], o);
    float v[4];
    bool valid = lane < 20;
    if (valid) {
#pragma unroll
        for (int k = 0; k < 4; k++) {
            float inv = 1.f / fmaxf(dn[hk[k]], 1e-35f);
            v[k] = acc[k] * inv + b2[c0 + k];
        }
    }
    float lm = valid ? fmaxf(fmaxf(v[0], v[1]), fmaxf(v[2], v[3])) : -INFINITY;
#pragma unroll
    for (int o = 16; o; o >>= 1) lm = fmaxf(lm, __shfl_xor_sync(0xFFFFFFFFu, lm, o));
    float se = valid ? (expf(v[0]-lm) + expf(v[1]-lm) + expf(v[2]-lm) + expf(v[3]-lm)) : 0.f;
#pragma unroll
    for (int o = 16; o; o >>= 1) se += __shfl_xor_sync(0xFFFFFFFFu, se, o);
    float lse = lm + logf(se);
    if (valid) {
        float4 ov = make_float4(v[0]-lse, v[1]-lse, v[2]-lse, v[3]-lse);
        *(float4*)&out[(size_t)dst * 80 + c0] = ov;
    }
}

// ---------------- launcher ----------------------------------------------------
extern "C" void kernel_launch(void* const* d_in, const int* in_sizes, int n_in,
                              void* d_out, int out_size) {
    const float* x       = (const float*)d_in[0];
    const int*   ei      = (const int*)d_in[1];
    const float* W1      = (const float*)d_in[2];
    const float* as1     = (const float*)d_in[3];
    const float* ad1     = (const float*)d_in[4];
    const float* b1      = (const float*)d_in[5];
    const float* W2      = (const float*)d_in[6];
    const float* as2     = (const float*)d_in[7];
    const float* ad2     = (const float*)d_in[8];
    const float* b2      = (const float*)d_in[9];
    float* out           = (float*)d_out;

    const int E  = in_sizes[1] / 2;
    const int ET = E + NN;
    const int T = 256;

    k_zero<<<(NN + T - 1) / T, T>>>();
    k_hist<<<(ET + T - 1) / T, T>>>(ei, E, ET);
    k_scan<<<1, SCAN_T>>>();
    k_scatter<<<(ET + T - 1) / T, T>>>(ei, E, ET);

    k_gemm1<<<(NN + 127) / 128, 256>>>(x, W1);
    k_calcs1<<<(NN * HH + T - 1) / T, T>>>(as1, ad1);
    k_gat1<<<(NN + 7) / 8, 256>>>(b1);

    k_gemm2<<<(NN + 63) / 64, 256>>>(W2);
    k_calcs2<<<(NN * HH + T - 1) / T, T>>>(as2, ad2);
    k_gat2<<<(NN + 7) / 8, 256>>>(b2, out);
}

// round 7
// speedup vs baseline: 2.6588x; 1.1561x over previous
#include <cuda_runtime.h>
#include <math.h>

#define NN 100000
#define FIN 512
#define HH 8
#define D1 64
#define C1 8
#define D2 80
#define C2 10
#define MAXET 3300000   // E=3.2M + N self loops

// ---------------- scratch (device globals; no allocation allowed) ----------
__device__ float g_h1[(size_t)NN * D1];
__device__ float g_ss1[NN * HH];
__device__ float g_sd1[NN * HH];
__device__ float g_hid[(size_t)NN * D1];
__device__ float g_h2[(size_t)NN * D2];
__device__ float g_ss2[NN * HH];
__device__ float g_sd2[NN * HH];
__device__ float g_Ms[16];          // [0..7] layer1 per-head max(s_src), [8..15] layer2
__device__ int   g_deg[NN];
__device__ int   g_off[NN];
__device__ int   g_cur[NN];
__device__ int   g_bt[128];         // block totals for hierarchical scan
__device__ int   g_csrc[MAXET];     // src ids bucketed by dst

// ---------------- helpers ---------------------------------------------------
__device__ __forceinline__ void atomicMaxF(float* a, float v) {
    if (v >= 0.f) atomicMax((int*)a, __float_as_int(v));
    else          atomicMin((unsigned int*)a, __float_as_uint(v));
}
__device__ __forceinline__ float lrelu(float t) { return t > 0.f ? t : 0.2f * t; }

// ---------------- CSR build ---------------------------------------------------
__global__ void k_zero() {
    int i = blockIdx.x * blockDim.x + threadIdx.x;
    if (i < NN) g_deg[i] = 0;
    if (i < 16) g_Ms[i] = -INFINITY;
}
__global__ void k_hist(const int* __restrict__ ei, int E, int ET) {
    int e = blockIdx.x * blockDim.x + threadIdx.x;
    if (e >= ET) return;
    int dst = (e < E) ? ei[(size_t)E + e] : (e - E);
    atomicAdd(&g_deg[dst], 1);
}
// hierarchical scan: A) block-local exclusive scan + block totals
__global__ __launch_bounds__(1024) void k_scanA() {
    __shared__ int ws[32];
    int tid = threadIdx.x, lane = tid & 31, warp = tid >> 5;
    int i = blockIdx.x * 1024 + tid;
    int v = (i < NN) ? g_deg[i] : 0;
    int x = v;
#pragma unroll
    for (int o = 1; o < 32; o <<= 1) {
        int t = __shfl_up_sync(0xFFFFFFFFu, x, o);
        if (lane >= o) x += t;
    }
    if (lane == 31) ws[warp] = x;
    __syncthreads();
    if (warp == 0) {
        int y = ws[lane];
#pragma unroll
        for (int o = 1; o < 32; o <<= 1) {
            int t = __shfl_up_sync(0xFFFFFFFFu, y, o);
            if (lane >= o) y += t;
        }
        ws[lane] = y;
    }
    __syncthreads();
    int base = warp ? ws[warp - 1] : 0;
    int incl = base + x;
    if (i < NN) g_off[i] = incl - v;            // block-local exclusive
    if (tid == 1023) g_bt[blockIdx.x] = incl;   // block total
}
// B) scan the 98 block totals (single block)
__global__ __launch_bounds__(128) void k_scanB(int nb) {
    __shared__ int sh[128];
    int tid = threadIdx.x;
    int v = (tid < nb) ? g_bt[tid] : 0;
    sh[tid] = v;
    __syncthreads();
#pragma unroll
    for (int o = 1; o < 128; o <<= 1) {
        int t = (tid >= o) ? sh[tid - o] : 0;
        __syncthreads();
        sh[tid] += t;
        __syncthreads();
    }
    if (tid < nb) g_bt[tid] = sh[tid] - v;      // exclusive
}
// C) add block bases
__global__ __launch_bounds__(1024) void k_scanC() {
    int i = blockIdx.x * 1024 + threadIdx.x;
    if (i < NN) {
        int o = g_off[i] + g_bt[blockIdx.x];
        g_off[i] = o;
        g_cur[i] = o;
    }
}
__global__ void k_scatter(const int* __restrict__ ei, int E, int ET) {
    int e = blockIdx.x * blockDim.x + threadIdx.x;
    if (e >= ET) return;
    int src, dst;
    if (e < E) { src = ei[e]; dst = ei[(size_t)E + e]; }
    else       { src = dst = e - E; }
    int pos = atomicAdd(&g_cur[dst], 1);
    g_csrc[pos] = src;
}

// ---------------- GEMM1: h1 = x @ W1, double-buffered ------------------------
__global__ __launch_bounds__(256) void k_gemm1(const float* __restrict__ x,
                                               const float* __restrict__ W) {
    __shared__ float As[2][16][132];
    __shared__ float Bs[2][16][68];
    const int bm = blockIdx.x * 128;
    const int tid = threadIdx.x;
    const int tx = tid & 15, ty = tid >> 4;
    const int r0 = (tid * 2) >> 2, kq0 = ((tid * 2) & 3) * 4;
    const int r1 = (tid * 2 + 1) >> 2, kq1 = ((tid * 2 + 1) & 3) * 4;
    const int bkr = tid >> 4, bnc = (tid & 15) * 4;
    float4 pa0, pa1, pb;

    auto ldg = [&](int k0) {
        pa0 = (bm + r0 < NN) ? *(const float4*)&x[(size_t)(bm + r0) * FIN + k0 + kq0]
                             : make_float4(0.f, 0.f, 0.f, 0.f);
        pa1 = (bm + r1 < NN) ? *(const float4*)&x[(size_t)(bm + r1) * FIN + k0 + kq1]
                             : make_float4(0.f, 0.f, 0.f, 0.f);
        pb  = *(const float4*)&W[(size_t)(k0 + bkr) * 64 + bnc];
    };
    auto sts = [&](int b) {
        As[b][kq0 + 0][r0] = pa0.x; As[b][kq0 + 1][r0] = pa0.y;
        As[b][kq0 + 2][r0] = pa0.z; As[b][kq0 + 3][r0] = pa0.w;
        As[b][kq1 + 0][r1] = pa1.x; As[b][kq1 + 1][r1] = pa1.y;
        As[b][kq1 + 2][r1] = pa1.z; As[b][kq1 + 3][r1] = pa1.w;
        *(float4*)&Bs[b][bkr][bnc] = pb;
    };

    float acc[8][4] = {};
    auto compute = [&](int b) {
#pragma unroll
        for (int k = 0; k < 16; k++) {
            float4 a0 = *(const float4*)&As[b][k][ty * 8];
            float4 a1 = *(const float4*)&As[b][k][ty * 8 + 4];
            float4 bb = *(const float4*)&Bs[b][k][tx * 4];
            float av[8] = {a0.x, a0.y, a0.z, a0.w, a1.x, a1.y, a1.z, a1.w};
            float bv[4] = {bb.x, bb.y, bb.z, bb.w};
#pragma unroll
            for (int i = 0; i < 8; i++)
#pragma unroll
                for (int j = 0; j < 4; j++) acc[i][j] += av[i] * bv[j];
        }
    };

    ldg(0); sts(0); __syncthreads();
    int buf = 0;
    for (int k0 = 16; k0 < FIN; k0 += 16) {
        ldg(k0);
        compute(buf);
        sts(buf ^ 1);
        __syncthreads();
        buf ^= 1;
    }
    compute(buf);

#pragma unroll
    for (int i = 0; i < 8; i++) {
        int row = bm + ty * 8 + i;
        if (row < NN) {
            float4 v = make_float4(acc[i][0], acc[i][1], acc[i][2], acc[i][3]);
            *(float4*)&g_h1[(size_t)row * 64 + tx * 4] = v;
        }
    }
}

// ---------------- GEMM2: h2 = hid @ W2  (M=100000, K=64, N=80) ---------------
__global__ __launch_bounds__(256) void k_gemm2(const float* __restrict__ W) {
    __shared__ float As[64][68];
    __shared__ float Bs[64][80];
    const int bm = blockIdx.x * 64;
    const int tid = threadIdx.x;
    const int tx = tid & 15, ty = tid >> 4;
    for (int i = tid; i < 64 * 80; i += 256) Bs[i / 80][i % 80] = W[i];
    const int ar = tid >> 4, ac = (tid & 15) * 4;
#pragma unroll
    for (int rr = 0; rr < 4; rr++) {
        int row = ar + rr * 16;
        float4 v = make_float4(0.f, 0.f, 0.f, 0.f);
        if (bm + row < NN)
            v = *(const float4*)&g_hid[(size_t)(bm + row) * 64 + ac];
        As[ac + 0][row] = v.x; As[ac + 1][row] = v.y;
        As[ac + 2][row] = v.z; As[ac + 3][row] = v.w;
    }
    __syncthreads();
    float acc[4][5] = {};
#pragma unroll 8
    for (int k = 0; k < 64; k++) {
        float4 a4 = *(const float4*)&As[k][ty * 4];
        float av[4] = {a4.x, a4.y, a4.z, a4.w};
        float bv[5];
#pragma unroll
        for (int j = 0; j < 5; j++) bv[j] = Bs[k][tx * 5 + j];
#pragma unroll
        for (int i = 0; i < 4; i++)
#pragma unroll
            for (int j = 0; j < 5; j++) acc[i][j] += av[i] * bv[j];
    }
#pragma unroll
    for (int i = 0; i < 4; i++) {
        int row = bm + ty * 4 + i;
        if (row < NN) {
#pragma unroll
            for (int j = 0; j < 5; j++)
                g_h2[(size_t)row * 80 + tx * 5 + j] = acc[i][j];
        }
    }
}

// ---------------- attention scores + per-head global max of s_src ------------
__device__ __forceinline__ void calcs_body(const float* __restrict__ h,
                                           const float* __restrict__ asrc,
                                           const float* __restrict__ adst,
                                           float* __restrict__ ss,
                                           float* __restrict__ sd,
                                           float* __restrict__ Ms,
                                           int C, int D) {
    __shared__ float red[8][9];
    int i = blockIdx.x * blockDim.x + threadIdx.x;
    int node = i >> 3, hh = i & 7;
    float a = -INFINITY, b = 0.f;
    if (i < NN * HH) {
        const float* hp = h + (size_t)node * D + hh * C;
        a = 0.f;
        for (int c = 0; c < C; c++) {
            float v = hp[c];
            a += v * asrc[hh * C + c];
            b += v * adst[hh * C + c];
        }
        ss[i] = a; sd[i] = b;
    }
    float mx = a;
    mx = fmaxf(mx, __shfl_xor_sync(0xFFFFFFFFu, mx, 8));
    mx = fmaxf(mx, __shfl_xor_sync(0xFFFFFFFFu, mx, 16));
    int warp = threadIdx.x >> 5, lane = threadIdx.x & 31;
    if (lane < 8) red[warp][lane] = mx;
    __syncthreads();
    if (warp == 0) {
        float v = red[lane & 7][0];
#pragma unroll
        for (int w = 1; w < 8; w++) v = fmaxf(v, red[lane & 7][w]);
        if (lane < 8) atomicMaxF(&Ms[lane], v);
    }
}
__global__ void k_calcs1(const float* __restrict__ as, const float* __restrict__ ad) {
    calcs_body(g_h1, as, ad, g_ss1, g_sd1, &g_Ms[0], C1, D1);
}
__global__ void k_calcs2(const float* __restrict__ as, const float* __restrict__ ad) {
    calcs_body(g_h2, as, ad, g_ss2, g_sd2, &g_Ms[8], C2, D2);
}

// ---------------- fused GAT layer 1: warp per dst, dual-edge gather ----------
__global__ __launch_bounds__(256) void k_gat1(const float* __restrict__ b1) {
    __shared__ int   s_src[8][32];
    __shared__ float s_ex[8][32][8];
    int w = threadIdx.x >> 5, lane = threadIdx.x & 31;
    int dst = blockIdx.x * 8 + w;
    if (dst >= NN) return;
    int off = g_off[dst], deg = g_deg[dst];
    float sdv[8], mb[8];
    {
        float4 t0 = *(const float4*)&g_sd1[(size_t)dst * 8];
        float4 t1 = *(const float4*)&g_sd1[(size_t)dst * 8 + 4];
        sdv[0]=t0.x; sdv[1]=t0.y; sdv[2]=t0.z; sdv[3]=t0.w;
        sdv[4]=t1.x; sdv[5]=t1.y; sdv[6]=t1.z; sdv[7]=t1.w;
#pragma unroll
        for (int h = 0; h < 8; h++) mb[h] = lrelu(__ldg(&g_Ms[h]) + sdv[h]);
    }
    float dn[8] = {0,0,0,0,0,0,0,0};
    float4 acc = make_float4(0.f, 0.f, 0.f, 0.f);
    const int cl = lane & 15;         // chunk (float4) index
    const int hl = cl >> 1;           // head for this chunk
    const int ehalf = lane >> 4;      // which edge of the pair
    for (int t = 0; t < deg; t += 32) {
        int j = t + lane;
        if (j < deg) {
            int src = g_csrc[off + j];
            s_src[w][lane] = src;
            float4 a0 = *(const float4*)&g_ss1[(size_t)src * 8];
            float4 a1 = *(const float4*)&g_ss1[(size_t)src * 8 + 4];
            float sv[8] = {a0.x, a0.y, a0.z, a0.w, a1.x, a1.y, a1.z, a1.w};
#pragma unroll
            for (int h = 0; h < 8; h++) {
                float ex = expf(lrelu(sv[h] + sdv[h]) - mb[h]);
                dn[h] += ex;
                s_ex[w][lane][h] = ex;
            }
        }
        __syncwarp();
        int cnt = min(32, deg - t);
        for (int jj = 0; jj < cnt; jj += 2) {
            int je = jj + ehalf;
            if (je < cnt) {
                int src = s_src[w][je];
                float4 hv = *(const float4*)&g_h1[(size_t)src * 64 + cl * 4];
                float ex = s_ex[w][je][hl];
                acc.x += hv.x * ex; acc.y += hv.y * ex;
                acc.z += hv.z * ex; acc.w += hv.w * ex;
            }
        }
        __syncwarp();
    }
    // combine the two edge-halves
    acc.x += __shfl_xor_sync(0xFFFFFFFFu, acc.x, 16);
    acc.y += __shfl_xor_sync(0xFFFFFFFFu, acc.y, 16);
    acc.z += __shfl_xor_sync(0xFFFFFFFFu, acc.z, 16);
    acc.w += __shfl_xor_sync(0xFFFFFFFFu, acc.w, 16);
#pragma unroll
    for (int h = 0; h < 8; h++)
#pragma unroll
        for (int o = 16; o; o >>= 1) dn[h] += __shfl_xor_sync(0xFFFFFFFFu, dn[h], o);
    if (lane < 16) {
        float inv = 1.f / fmaxf(dn[hl], 1e-35f);
        float4 bv = *(const float4*)&b1[lane * 4];
        float v[4] = {acc.x * inv + bv.x, acc.y * inv + bv.y,
                      acc.z * inv + bv.z, acc.w * inv + bv.w};
#pragma unroll
        for (int k = 0; k < 4; k++) v[k] = v[k] > 0.f ? v[k] : (expf(v[k]) - 1.f);
        *(float4*)&g_hid[(size_t)dst * 64 + lane * 4] = make_float4(v[0], v[1], v[2], v[3]);
    }
}

// ---------------- fused GAT layer 2 + log_softmax: warp per dst --------------
__global__ __launch_bounds__(256) void k_gat2(const float* __restrict__ b2,
                                              float* __restrict__ out) {
    __shared__ int   s_src[8][32];
    __shared__ float s_ex[8][32][8];
    int w = threadIdx.x >> 5, lane = threadIdx.x & 31;
    int dst = blockIdx.x * 8 + w;
    if (dst >= NN) return;
    int off = g_off[dst], deg = g_deg[dst];
    float sdv[8], mb[8];
    {
        float4 t0 = *(const float4*)&g_sd2[(size_t)dst * 8];
        float4 t1 = *(const float4*)&g_sd2[(size_t)dst * 8 + 4];
        sdv[0]=t0.x; sdv[1]=t0.y; sdv[2]=t0.z; sdv[3]=t0.w;
        sdv[4]=t1.x; sdv[5]=t1.y; sdv[6]=t1.z; sdv[7]=t1.w;
#pragma unroll
        for (int h = 0; h < 8; h++) mb[h] = lrelu(__ldg(&g_Ms[8 + h]) + sdv[h]);
    }
    float dn[8] = {0,0,0,0,0,0,0,0};
    float acc0[4] = {0.f, 0.f, 0.f, 0.f};
    float acc1[4] = {0.f, 0.f, 0.f, 0.f};
    const int c0 = lane * 4;
    int hk[4];
#pragma unroll
    for (int k = 0; k < 4; k++) hk[k] = (c0 + k) / 10;
    for (int t = 0; t < deg; t += 32) {
        int j = t + lane;
        if (j < deg) {
            int src = g_csrc[off + j];
            s_src[w][lane] = src;
            float4 a0 = *(const float4*)&g_ss2[(size_t)src * 8];
            float4 a1 = *(const float4*)&g_ss2[(size_t)src * 8 + 4];
            float sv[8] = {a0.x, a0.y, a0.z, a0.w, a1.x, a1.y, a1.z, a1.w};
#pragma unroll
            for (int h = 0; h < 8; h++) {
                float ex = expf(lrelu(sv[h] + sdv[h]) - mb[h]);
                dn[h] += ex;
                s_ex[w][lane][h] = ex;
            }
        }
        __syncwarp();
        int cnt = min(32, deg - t);
        if (lane < 20) {
            int jj = 0;
            for (; jj + 1 < cnt; jj += 2) {
                int sa = s_src[w][jj], sb = s_src[w][jj + 1];
                float4 ha = *(const float4*)&g_h2[(size_t)sa * 80 + c0];
                float4 hb = *(const float4*)&g_h2[(size_t)sb * 80 + c0];
                acc0[0] += ha.x * s_ex[w][jj][hk[0]];
                acc0[1] += ha.y * s_ex[w][jj][hk[1]];
                acc0[2] += ha.z * s_ex[w][jj][hk[2]];
                acc0[3] += ha.w * s_ex[w][jj][hk[3]];
                acc1[0] += hb.x * s_ex[w][jj + 1][hk[0]];
                acc1[1] += hb.y * s_ex[w][jj + 1][hk[1]];
                acc1[2] += hb.z * s_ex[w][jj + 1][hk[2]];
                acc1[3] += hb.w * s_ex[w][jj + 1][hk[3]];
            }
            if (jj < cnt) {
                int sa = s_src[w][jj];
                float4 ha = *(const float4*)&g_h2[(size_t)sa * 80 + c0];
                acc0[0] += ha.x * s_ex[w][jj][hk[0]];
                acc0[1] += ha.y * s_ex[w][jj][hk[1]];
                acc0[2] += ha.z * s_ex[w][jj][hk[2]];
                acc0[3] += ha.w * s_ex[w][jj][hk[3]];
            }
        }
        __syncwarp();
    }
#pragma unroll
    for (int h = 0; h < 8; h++)
#pragma unroll
        for (int o = 16; o; o >>= 1) dn[h] += __shfl_xor_sync(0xFFFFFFFFu, dn[h], o);
    float v[4];
    bool valid = lane < 20;
    if (valid) {
#pragma unroll
        for (int k = 0; k < 4; k++) {
            float inv = 1.f / fmaxf(dn[hk[k]], 1e-35f);
            v[k] = (acc0[k] + acc1[k]) * inv + b2[c0 + k];
        }
    }
    float lm = valid ? fmaxf(fmaxf(v[0], v[1]), fmaxf(v[2], v[3])) : -INFINITY;
#pragma unroll
    for (int o = 16; o; o >>= 1) lm = fmaxf(lm, __shfl_xor_sync(0xFFFFFFFFu, lm, o));
    float se = valid ? (expf(v[0]-lm) + expf(v[1]-lm) + expf(v[2]-lm) + expf(v[3]-lm)) : 0.f;
#pragma unroll
    for (int o = 16; o; o >>= 1) se += __shfl_xor_sync(0xFFFFFFFFu, se, o);
    float lse = lm + logf(se);
    if (valid) {
        float4 ov = make_float4(v[0]-lse, v[1]-lse, v[2]-lse, v[3]-lse);
        *(float4*)&out[(size_t)dst * 80 + c0] = ov;
    }
}

// ---------------- launcher ----------------------------------------------------
extern "C" void kernel_launch(void* const* d_in, const int* in_sizes, int n_in,
                              void* d_out, int out_size) {
    const float* x       = (const float*)d_in[0];
    const int*   ei      = (const int*)d_in[1];
    const float* W1      = (const float*)d_in[2];
    const float* as1     = (const float*)d_in[3];
    const float* ad1     = (const float*)d_in[4];
    const float* b1      = (const float*)d_in[5];
    const float* W2      = (const float*)d_in[6];
    const float* as2     = (const float*)d_in[7];
    const float* ad2     = (const float*)d_in[8];
    const float* b2      = (const float*)d_in[9];
    float* out           = (float*)d_out;

    const int E  = in_sizes[1] / 2;
    const int ET = E + NN;
    const int T = 256;
    const int NB = (NN + 1023) / 1024;

    k_zero<<<(NN + T - 1) / T, T>>>();
    k_hist<<<(ET + T - 1) / T, T>>>(ei, E, ET);
    k_scanA<<<NB, 1024>>>();
    k_scanB<<<1, 128>>>(NB);
    k_scanC<<<NB, 1024>>>();
    k_scatter<<<(ET + T - 1) / T, T>>>(ei, E, ET);

    k_gemm1<<<(NN + 127) / 128, 256>>>(x, W1);
    k_calcs1<<<(NN * HH + T - 1) / T, T>>>(as1, ad1);
    k_gat1<<<(NN + 7) / 8, 256>>>(b1);

    k_gemm2<<<(NN + 63) / 64, 256>>>(W2);
    k_calcs2<<<(NN * HH + T - 1) / T, T>>>(as2, ad2);
    k_gat2<<<(NN + 7) / 8, 256>>>(b2, out);
}

// round 8
// speedup vs baseline: 3.1598x; 1.1884x over previous
#include <cuda_runtime.h>
#include <cuda_fp16.h>
#include <math.h>

#define NN 100000
#define FIN 512
#define HH 8
#define D1 64
#define C1 8
#define D2 80
#define C2 10
#define MAXET 3300000   // E=3.2M + N self loops

// ---------------- scratch (device globals; no allocation allowed) ----------
__device__ __half g_h1[(size_t)NN * D1];
__device__ float  g_ss1[NN * HH];
__device__ float  g_sd1[NN * HH];
__device__ float  g_hid[(size_t)NN * D1];
__device__ __half g_h2[(size_t)NN * D2];
__device__ float  g_ss2[NN * HH];
__device__ float  g_sd2[NN * HH];
__device__ float  g_Ms[16];
__device__ int    g_deg[NN];
__device__ int    g_off[NN];
__device__ int    g_cur[NN];
__device__ int    g_bt[128];
__device__ int    g_csrc[MAXET];

// ---------------- helpers ---------------------------------------------------
__device__ __forceinline__ void atomicMaxF(float* a, float v) {
    if (v >= 0.f) atomicMax((int*)a, __float_as_int(v));
    else          atomicMin((unsigned int*)a, __float_as_uint(v));
}
__device__ __forceinline__ float lrelu(float t) { return t > 0.f ? t : 0.2f * t; }

// ---------------- CSR build ---------------------------------------------------
__global__ void k_zero() {
    int i = blockIdx.x * blockDim.x + threadIdx.x;
    if (i < NN) g_deg[i] = 0;
    if (i < 16) g_Ms[i] = -INFINITY;
}
__global__ void k_hist(const int* __restrict__ ei, int E, int ET) {
    int e = blockIdx.x * blockDim.x + threadIdx.x;
    if (e >= ET) return;
    int dst = (e < E) ? ei[(size_t)E + e] : (e - E);
    atomicAdd(&g_deg[dst], 1);
}
__global__ __launch_bounds__(1024) void k_scanA() {
    __shared__ int ws[32];
    int tid = threadIdx.x, lane = tid & 31, warp = tid >> 5;
    int i = blockIdx.x * 1024 + tid;
    int v = (i < NN) ? g_deg[i] : 0;
    int x = v;
#pragma unroll
    for (int o = 1; o < 32; o <<= 1) {
        int t = __shfl_up_sync(0xFFFFFFFFu, x, o);
        if (lane >= o) x += t;
    }
    if (lane == 31) ws[warp] = x;
    __syncthreads();
    if (warp == 0) {
        int y = ws[lane];
#pragma unroll
        for (int o = 1; o < 32; o <<= 1) {
            int t = __shfl_up_sync(0xFFFFFFFFu, y, o);
            if (lane >= o) y += t;
        }
        ws[lane] = y;
    }
    __syncthreads();
    int base = warp ? ws[warp - 1] : 0;
    int incl = base + x;
    if (i < NN) g_off[i] = incl - v;
    if (tid == 1023) g_bt[blockIdx.x] = incl;
}
__global__ __launch_bounds__(128) void k_scanB(int nb) {
    __shared__ int sh[128];
    int tid = threadIdx.x;
    int v = (tid < nb) ? g_bt[tid] : 0;
    sh[tid] = v;
    __syncthreads();
#pragma unroll
    for (int o = 1; o < 128; o <<= 1) {
        int t = (tid >= o) ? sh[tid - o] : 0;
        __syncthreads();
        sh[tid] += t;
        __syncthreads();
    }
    if (tid < nb) g_bt[tid] = sh[tid] - v;
}
__global__ __launch_bounds__(1024) void k_scanC() {
    int i = blockIdx.x * 1024 + threadIdx.x;
    if (i < NN) {
        int o = g_off[i] + g_bt[blockIdx.x];
        g_off[i] = o;
        g_cur[i] = o;
    }
}
__global__ void k_scatter(const int* __restrict__ ei, int E, int ET) {
    int e = blockIdx.x * blockDim.x + threadIdx.x;
    if (e >= ET) return;
    int src, dst;
    if (e < E) { src = ei[e]; dst = ei[(size_t)E + e]; }
    else       { src = dst = e - E; }
    int pos = atomicAdd(&g_cur[dst], 1);
    g_csrc[pos] = src;
}

// ---------------- GEMM1: h1 = x @ W1 (fp16 out), double-buffered -------------
__global__ __launch_bounds__(256) void k_gemm1(const float* __restrict__ x,
                                               const float* __restrict__ W) {
    __shared__ float As[2][16][132];
    __shared__ float Bs[2][16][68];
    const int bm = blockIdx.x * 128;
    const int tid = threadIdx.x;
    const int tx = tid & 15, ty = tid >> 4;
    const int r0 = (tid * 2) >> 2, kq0 = ((tid * 2) & 3) * 4;
    const int r1 = (tid * 2 + 1) >> 2, kq1 = ((tid * 2 + 1) & 3) * 4;
    const int bkr = tid >> 4, bnc = (tid & 15) * 4;
    float4 pa0, pa1, pb;

    auto ldg = [&](int k0) {
        pa0 = (bm + r0 < NN) ? *(const float4*)&x[(size_t)(bm + r0) * FIN + k0 + kq0]
                             : make_float4(0.f, 0.f, 0.f, 0.f);
        pa1 = (bm + r1 < NN) ? *(const float4*)&x[(size_t)(bm + r1) * FIN + k0 + kq1]
                             : make_float4(0.f, 0.f, 0.f, 0.f);
        pb  = *(const float4*)&W[(size_t)(k0 + bkr) * 64 + bnc];
    };
    auto sts = [&](int b) {
        As[b][kq0 + 0][r0] = pa0.x; As[b][kq0 + 1][r0] = pa0.y;
        As[b][kq0 + 2][r0] = pa0.z; As[b][kq0 + 3][r0] = pa0.w;
        As[b][kq1 + 0][r1] = pa1.x; As[b][kq1 + 1][r1] = pa1.y;
        As[b][kq1 + 2][r1] = pa1.z; As[b][kq1 + 3][r1] = pa1.w;
        *(float4*)&Bs[b][bkr][bnc] = pb;
    };

    float acc[8][4] = {};
    auto compute = [&](int b) {
#pragma unroll
        for (int k = 0; k < 16; k++) {
            float4 a0 = *(const float4*)&As[b][k][ty * 8];
            float4 a1 = *(const float4*)&As[b][k][ty * 8 + 4];
            float4 bb = *(const float4*)&Bs[b][k][tx * 4];
            float av[8] = {a0.x, a0.y, a0.z, a0.w, a1.x, a1.y, a1.z, a1.w};
            float bv[4] = {bb.x, bb.y, bb.z, bb.w};
#pragma unroll
            for (int i = 0; i < 8; i++)
#pragma unroll
                for (int j = 0; j < 4; j++) acc[i][j] += av[i] * bv[j];
        }
    };

    ldg(0); sts(0); __syncthreads();
    int buf = 0;
    for (int k0 = 16; k0 < FIN; k0 += 16) {
        ldg(k0);
        compute(buf);
        sts(buf ^ 1);
        __syncthreads();
        buf ^= 1;
    }
    compute(buf);

#pragma unroll
    for (int i = 0; i < 8; i++) {
        int row = bm + ty * 8 + i;
        if (row < NN) {
            __half2* p = (__half2*)&g_h1[(size_t)row * 64 + tx * 4];
            p[0] = __floats2half2_rn(acc[i][0], acc[i][1]);
            p[1] = __floats2half2_rn(acc[i][2], acc[i][3]);
        }
    }
}

// ---------------- GEMM2: h2 = hid @ W2 (fp16 out) ----------------------------
__global__ __launch_bounds__(256) void k_gemm2(const float* __restrict__ W) {
    __shared__ float As[64][68];
    __shared__ float Bs[64][80];
    const int bm = blockIdx.x * 64;
    const int tid = threadIdx.x;
    const int tx = tid & 15, ty = tid >> 4;
    for (int i = tid; i < 64 * 80; i += 256) Bs[i / 80][i % 80] = W[i];
    const int ar = tid >> 4, ac = (tid & 15) * 4;
#pragma unroll
    for (int rr = 0; rr < 4; rr++) {
        int row = ar + rr * 16;
        float4 v = make_float4(0.f, 0.f, 0.f, 0.f);
        if (bm + row < NN)
            v = *(const float4*)&g_hid[(size_t)(bm + row) * 64 + ac];
        As[ac + 0][row] = v.x; As[ac + 1][row] = v.y;
        As[ac + 2][row] = v.z; As[ac + 3][row] = v.w;
    }
    __syncthreads();
    float acc[4][5] = {};
#pragma unroll 8
    for (int k = 0; k < 64; k++) {
        float4 a4 = *(const float4*)&As[k][ty * 4];
        float av[4] = {a4.x, a4.y, a4.z, a4.w};
        float bv[5];
#pragma unroll
        for (int j = 0; j < 5; j++) bv[j] = Bs[k][tx * 5 + j];
#pragma unroll
        for (int i = 0; i < 4; i++)
#pragma unroll
            for (int j = 0; j < 5; j++) acc[i][j] += av[i] * bv[j];
    }
#pragma unroll
    for (int i = 0; i < 4; i++) {
        int row = bm + ty * 4 + i;
        if (row < NN) {
#pragma unroll
            for (int j = 0; j < 5; j++)
                g_h2[(size_t)row * 80 + tx * 5 + j] = __float2half_rn(acc[i][j]);
        }
    }
}

// ---------------- attention scores + per-head global max of s_src ------------
__device__ __forceinline__ void calcs_body(const __half* __restrict__ h,
                                           const float* __restrict__ asrc,
                                           const float* __restrict__ adst,
                                           float* __restrict__ ss,
                                           float* __restrict__ sd,
                                           float* __restrict__ Ms,
                                           int C, int D) {
    __shared__ float red[8][9];
    int i = blockIdx.x * blockDim.x + threadIdx.x;
    int node = i >> 3, hh = i & 7;
    float a = -INFINITY, b = 0.f;
    if (i < NN * HH) {
        const __half2* hp = (const __half2*)(h + (size_t)node * D + hh * C);
        a = 0.f;
        for (int c = 0; c < C / 2; c++) {
            float2 v = __half22float2(hp[c]);
            a += v.x * asrc[hh * C + 2 * c] + v.y * asrc[hh * C + 2 * c + 1];
            b += v.x * adst[hh * C + 2 * c] + v.y * adst[hh * C + 2 * c + 1];
        }
        ss[i] = a; sd[i] = b;
    }
    float mx = a;
    mx = fmaxf(mx, __shfl_xor_sync(0xFFFFFFFFu, mx, 8));
    mx = fmaxf(mx, __shfl_xor_sync(0xFFFFFFFFu, mx, 16));
    int warp = threadIdx.x >> 5, lane = threadIdx.x & 31;
    if (lane < 8) red[warp][lane] = mx;
    __syncthreads();
    if (warp == 0) {
        float v = red[lane & 7][0];
#pragma unroll
        for (int w = 1; w < 8; w++) v = fmaxf(v, red[lane & 7][w]);
        if (lane < 8) atomicMaxF(&Ms[lane], v);
    }
}
__global__ void k_calcs1(const float* __restrict__ as, const float* __restrict__ ad) {
    calcs_body(g_h1, as, ad, g_ss1, g_sd1, &g_Ms[0], C1, D1);
}
__global__ void k_calcs2(const float* __restrict__ as, const float* __restrict__ ad) {
    calcs_body(g_h2, as, ad, g_ss2, g_sd2, &g_Ms[8], C2, D2);
}

// ---------------- fused GAT layer 1: warp/dst, fp16 gather, 4 edges/iter -----
__global__ __launch_bounds__(256) void k_gat1(const float* __restrict__ b1) {
    __shared__ int   s_src[8][32];
    __shared__ float s_ex[8][32][8];
    int w = threadIdx.x >> 5, lane = threadIdx.x & 31;
    int dst = blockIdx.x * 8 + w;
    if (dst >= NN) return;
    int off = g_off[dst], deg = g_deg[dst];
    float sdv[8], mb[8];
    {
        float4 t0 = *(const float4*)&g_sd1[(size_t)dst * 8];
        float4 t1 = *(const float4*)&g_sd1[(size_t)dst * 8 + 4];
        sdv[0]=t0.x; sdv[1]=t0.y; sdv[2]=t0.z; sdv[3]=t0.w;
        sdv[4]=t1.x; sdv[5]=t1.y; sdv[6]=t1.z; sdv[7]=t1.w;
#pragma unroll
        for (int h = 0; h < 8; h++) mb[h] = lrelu(__ldg(&g_Ms[h]) + sdv[h]);
    }
    float dn[8] = {0,0,0,0,0,0,0,0};
    float acc[8] = {0,0,0,0,0,0,0,0};
    const int c = lane & 7;           // chunk == head (8 halves per chunk, C1=8)
    const int eidx = lane >> 3;       // 4 edges per iteration
    for (int t = 0; t < deg; t += 32) {
        int j = t + lane;
        if (j < deg) {
            int src = g_csrc[off + j];
            s_src[w][lane] = src;
            float4 a0 = *(const float4*)&g_ss1[(size_t)src * 8];
            float4 a1 = *(const float4*)&g_ss1[(size_t)src * 8 + 4];
            float sv[8] = {a0.x, a0.y, a0.z, a0.w, a1.x, a1.y, a1.z, a1.w};
#pragma unroll
            for (int h = 0; h < 8; h++) {
                float ex = expf(lrelu(sv[h] + sdv[h]) - mb[h]);
                dn[h] += ex;
                s_ex[w][lane][h] = ex;
            }
        }
        __syncwarp();
        int cnt = min(32, deg - t);
        for (int jj = 0; jj < cnt; jj += 4) {
            int je = jj + eidx;
            if (je < cnt) {
                int src = s_src[w][je];
                uint4 u = *(const uint4*)&g_h1[(size_t)src * 64 + c * 8];
                float ex = s_ex[w][je][c];
                const __half2* hp = (const __half2*)&u;
#pragma unroll
                for (int q = 0; q < 4; q++) {
                    float2 f = __half22float2(hp[q]);
                    acc[2 * q]     += f.x * ex;
                    acc[2 * q + 1] += f.y * ex;
                }
            }
        }
        __syncwarp();
    }
#pragma unroll
    for (int k = 0; k < 8; k++) {
        acc[k] += __shfl_xor_sync(0xFFFFFFFFu, acc[k], 8);
        acc[k] += __shfl_xor_sync(0xFFFFFFFFu, acc[k], 16);
    }
#pragma unroll
    for (int h = 0; h < 8; h++)
#pragma unroll
        for (int o = 16; o; o >>= 1) dn[h] += __shfl_xor_sync(0xFFFFFFFFu, dn[h], o);
    if (lane < 8) {
        float inv = 1.f / fmaxf(dn[lane], 1e-35f);
        float v[8];
#pragma unroll
        for (int k = 0; k < 8; k++) {
            v[k] = acc[k] * inv + b1[lane * 8 + k];
            v[k] = v[k] > 0.f ? v[k] : (expf(v[k]) - 1.f);
        }
        float4* p = (float4*)&g_hid[(size_t)dst * 64 + lane * 8];
        p[0] = make_float4(v[0], v[1], v[2], v[3]);
        p[1] = make_float4(v[4], v[5], v[6], v[7]);
    }
}

// ---------------- fused GAT layer 2 + log_softmax: fp16 gather, 3 edges/iter -
__global__ __launch_bounds__(256) void k_gat2(const float* __restrict__ b2,
                                              float* __restrict__ out) {
    __shared__ int   s_src[8][32];
    __shared__ float s_ex[8][32][8];
    int w = threadIdx.x >> 5, lane = threadIdx.x & 31;
    int dst = blockIdx.x * 8 + w;
    if (dst >= NN) return;
    int off = g_off[dst], deg = g_deg[dst];
    float sdv[8], mb[8];
    {
        float4 t0 = *(const float4*)&g_sd2[(size_t)dst * 8];
        float4 t1 = *(const float4*)&g_sd2[(size_t)dst * 8 + 4];
        sdv[0]=t0.x; sdv[1]=t0.y; sdv[2]=t0.z; sdv[3]=t0.w;
        sdv[4]=t1.x; sdv[5]=t1.y; sdv[6]=t1.z; sdv[7]=t1.w;
#pragma unroll
        for (int h = 0; h < 8; h++) mb[h] = lrelu(__ldg(&g_Ms[8 + h]) + sdv[h]);
    }
    float dn[8] = {0,0,0,0,0,0,0,0};
    float acc[8] = {0,0,0,0,0,0,0,0};
    const int eidx = lane / 10;                  // 3 edges per iteration
    const int c = lane - eidx * 10;              // chunk 0..9 (8 halves each)
    const bool gactive = lane < 30;
    int hk[8];
#pragma unroll
    for (int k = 0; k < 8; k++) hk[k] = (c * 8 + k) / 10;
    for (int t = 0; t < deg; t += 32) {
        int j = t + lane;
        if (j < deg) {
            int src = g_csrc[off + j];
            s_src[w][lane] = src;
            float4 a0 = *(const float4*)&g_ss2[(size_t)src * 8];
            float4 a1 = *(const float4*)&g_ss2[(size_t)src * 8 + 4];
            float sv[8] = {a0.x, a0.y, a0.z, a0.w, a1.x, a1.y, a1.z, a1.w};
#pragma unroll
            for (int h = 0; h < 8; h++) {
                float ex = expf(lrelu(sv[h] + sdv[h]) - mb[h]);
                dn[h] += ex;
                s_ex[w][lane][h] = ex;
            }
        }
        __syncwarp();
        int cnt = min(32, deg - t);
        for (int jj = 0; jj < cnt; jj += 3) {
            int je = jj + eidx;
            if (gactive && je < cnt) {
                int src = s_src[w][je];
                uint4 u = *(const uint4*)&g_h2[(size_t)src * 80 + c * 8];
                const __half2* hp = (const __half2*)&u;
#pragma unroll
                for (int q = 0; q < 4; q++) {
                    float2 f = __half22float2(hp[q]);
                    acc[2 * q]     += f.x * s_ex[w][je][hk[2 * q]];
                    acc[2 * q + 1] += f.y * s_ex[w][je][hk[2 * q + 1]];
                }
            }
        }
        __syncwarp();
    }
    // combine 3 edge groups: lanes 0..9 += lanes +10, +20
#pragma unroll
    for (int k = 0; k < 8; k++) {
        float v10 = __shfl_sync(0xFFFFFFFFu, acc[k], (lane + 10) & 31);
        float v20 = __shfl_sync(0xFFFFFFFFu, acc[k], (lane + 20) & 31);
        if (lane < 10) acc[k] += v10 + v20;
    }
#pragma unroll
    for (int h = 0; h < 8; h++)
#pragma unroll
        for (int o = 16; o; o >>= 1) dn[h] += __shfl_xor_sync(0xFFFFFFFFu, dn[h], o);
    bool valid = lane < 10;
    float v[8];
    float lm = -INFINITY;
    if (valid) {
#pragma unroll
        for (int k = 0; k < 8; k++) {
            float inv = 1.f / fmaxf(dn[hk[k]], 1e-35f);
            v[k] = acc[k] * inv + b2[c * 8 + k];
            lm = fmaxf(lm, v[k]);
        }
    }
#pragma unroll
    for (int o = 16; o; o >>= 1) lm = fmaxf(lm, __shfl_xor_sync(0xFFFFFFFFu, lm, o));
    float se = 0.f;
    if (valid) {
#pragma unroll
        for (int k = 0; k < 8; k++) se += expf(v[k] - lm);
    }
#pragma unroll
    for (int o = 16; o; o >>= 1) se += __shfl_xor_sync(0xFFFFFFFFu, se, o);
    float lse = lm + logf(se);
    if (valid) {
        float4* p = (float4*)&out[(size_t)dst * 80 + c * 8];
        p[0] = make_float4(v[0] - lse, v[1] - lse, v[2] - lse, v[3] - lse);
        p[1] = make_float4(v[4] - lse, v[5] - lse, v[6] - lse, v[7] - lse);
    }
}

// ---------------- launcher ----------------------------------------------------
extern "C" void kernel_launch(void* const* d_in, const int* in_sizes, int n_in,
                              void* d_out, int out_size) {
    const float* x       = (const float*)d_in[0];
    const int*   ei      = (const int*)d_in[1];
    const float* W1      = (const float*)d_in[2];
    const float* as1     = (const float*)d_in[3];
    const float* ad1     = (const float*)d_in[4];
    const float* b1      = (const float*)d_in[5];
    const float* W2      = (const float*)d_in[6];
    const float* as2     = (const float*)d_in[7];
    const float* ad2     = (const float*)d_in[8];
    const float* b2      = (const float*)d_in[9];
    float* out           = (float*)d_out;

    const int E  = in_sizes[1] / 2;
    const int ET = E + NN;
    const int T = 256;
    const int NB = (NN + 1023) / 1024;

    k_zero<<<(NN + T - 1) / T, T>>>();
    k_hist<<<(ET + T - 1) / T, T>>>(ei, E, ET);
    k_scanA<<<NB, 1024>>>();
    k_scanB<<<1, 128>>>(NB);
    k_scanC<<<NB, 1024>>>();
    k_scatter<<<(ET + T - 1) / T, T>>>(ei, E, ET);

    k_gemm1<<<(NN + 127) / 128, 256>>>(x, W1);
    k_calcs1<<<(NN * HH + T - 1) / T, T>>>(as1, ad1);
    k_gat1<<<(NN + 7) / 8, 256>>>(b1);

    k_gemm2<<<(NN + 63) / 64, 256>>>(W2);
    k_calcs2<<<(NN * HH + T - 1) / T, T>>>(as2, ad2);
    k_gat2<<<(NN + 7) / 8, 256>>>(b2, out);
}

// round 12
// speedup vs baseline: 3.6967x; 1.1699x over previous
#include <cuda_runtime.h>
#include <cuda_fp16.h>
#include <stdint.h>
#include <math.h>

#define NN 100000
#define FIN 512
#define HH 8
#define D1 64
#define C1 8
#define D2 80
#define C2 10
#define MAXET 3300000   // E=3.2M + N self loops

// ---------------- scratch (device globals; no allocation allowed) ----------
__device__ __half g_h1[(size_t)NN * D1];
__device__ float  g_ss1[NN * HH];
__device__ float  g_sd1[NN * HH];
__device__ float  g_hid[(size_t)NN * D1];
__device__ __half g_h2[(size_t)NN * D2];
__device__ float  g_ss2[NN * HH];
__device__ float  g_sd2[NN * HH];
__device__ float  g_Ms[16];
__device__ int    g_deg[NN];
__device__ int    g_off[NN];
__device__ int    g_cur[NN];
__device__ int    g_bt[128];
__device__ int    g_csrc[MAXET];

// ---------------- helpers ---------------------------------------------------
__device__ __forceinline__ void atomicMaxF(float* a, float v) {
    if (v >= 0.f) atomicMax((int*)a, __float_as_int(v));
    else          atomicMin((unsigned int*)a, __float_as_uint(v));
}
__device__ __forceinline__ float lrelu(float t) { return t > 0.f ? t : 0.2f * t; }

// ---- mma plumbing: plain functions, scalar refs (nvcc-safe asm) --------------
__device__ __forceinline__ void ldsm_x4(uint32_t addr, uint32_t& r0, uint32_t& r1,
                                        uint32_t& r2, uint32_t& r3) {
    asm volatile("ldmatrix.sync.aligned.m8n8.x4.shared.b16 {%0,%1,%2,%3}, [%4];"
                 : "=r"(r0), "=r"(r1), "=r"(r2), "=r"(r3) : "r"(addr));
}
__device__ __forceinline__ void ldsm_x4_t(uint32_t addr, uint32_t& r0, uint32_t& r1,
                                          uint32_t& r2, uint32_t& r3) {
    asm volatile("ldmatrix.sync.aligned.m8n8.x4.trans.shared.b16 {%0,%1,%2,%3}, [%4];"
                 : "=r"(r0), "=r"(r1), "=r"(r2), "=r"(r3) : "r"(addr));
}
__device__ __forceinline__ void mma16816(float& d0, float& d1, float& d2, float& d3,
                                         uint32_t a0, uint32_t a1, uint32_t a2, uint32_t a3,
                                         uint32_t b0, uint32_t b1) {
    asm volatile("mma.sync.aligned.m16n8k16.row.col.f32.f16.f16.f32 "
                 "{%0,%1,%2,%3}, {%4,%5,%6,%7}, {%8,%9}, {%0,%1,%2,%3};"
                 : "+f"(d0), "+f"(d1), "+f"(d2), "+f"(d3)
                 : "r"(a0), "r"(a1), "r"(a2), "r"(a3), "r"(b0), "r"(b1));
}

// ---------------- CSR build ---------------------------------------------------
__global__ void k_zero() {
    int i = blockIdx.x * blockDim.x + threadIdx.x;
    if (i < NN) g_deg[i] = 0;
    if (i < 16) g_Ms[i] = -INFINITY;
}
__global__ void k_hist(const int* __restrict__ ei, int E, int ET) {
    int e = blockIdx.x * blockDim.x + threadIdx.x;
    if (e >= ET) return;
    int dst = (e < E) ? ei[(size_t)E + e] : (e - E);
    atomicAdd(&g_deg[dst], 1);
}
__global__ __launch_bounds__(1024) void k_scanA() {
    __shared__ int ws[32];
    int tid = threadIdx.x, lane = tid & 31, warp = tid >> 5;
    int i = blockIdx.x * 1024 + tid;
    int v = (i < NN) ? g_deg[i] : 0;
    int x = v;
#pragma unroll
    for (int o = 1; o < 32; o <<= 1) {
        int t = __shfl_up_sync(0xFFFFFFFFu, x, o);
        if (lane >= o) x += t;
    }
    if (lane == 31) ws[warp] = x;
    __syncthreads();
    if (warp == 0) {
        int y = ws[lane];
#pragma unroll
        for (int o = 1; o < 32; o <<= 1) {
            int t = __shfl_up_sync(0xFFFFFFFFu, y, o);
            if (lane >= o) y += t;
        }
        ws[lane] = y;
    }
    __syncthreads();
    int base = warp ? ws[warp - 1] : 0;
    int incl = base + x;
    if (i < NN) g_off[i] = incl - v;
    if (tid == 1023) g_bt[blockIdx.x] = incl;
}
__global__ __launch_bounds__(128) void k_scanB(int nb) {
    __shared__ int sh[128];
    int tid = threadIdx.x;
    int v = (tid < nb) ? g_bt[tid] : 0;
    sh[tid] = v;
    __syncthreads();
#pragma unroll
    for (int o = 1; o < 128; o <<= 1) {
        int t = (tid >= o) ? sh[tid - o] : 0;
        __syncthreads();
        sh[tid] += t;
        __syncthreads();
    }
    if (tid < nb) g_bt[tid] = sh[tid] - v;
}
__global__ __launch_bounds__(1024) void k_scanC() {
    int i = blockIdx.x * 1024 + threadIdx.x;
    if (i < NN) {
        int o = g_off[i] + g_bt[blockIdx.x];
        g_off[i] = o;
        g_cur[i] = o;
    }
}
__global__ void k_scatter(const int* __restrict__ ei, int E, int ET) {
    int e = blockIdx.x * blockDim.x + threadIdx.x;
    if (e >= ET) return;
    int src, dst;
    if (e < E) { src = ei[e]; dst = ei[(size_t)E + e]; }
    else       { src = dst = e - E; }
    int pos = atomicAdd(&g_cur[dst], 1);
    g_csrc[pos] = src;
}

// ------- GEMM1: h1 = x @ W1 via mma.sync m16n8k16 fp16 (fp32 accum) ----------
__device__ __forceinline__ void gemm1_compute(uint32_t baseA, uint32_t baseB,
                                              int wm, int wn, int lane,
                                              float (&acc)[2][4][4]) {
#pragma unroll
    for (int ks = 0; ks < 2; ks++) {
        uint32_t af[2][4], bf[2][4];
#pragma unroll
        for (int mi = 0; mi < 2; mi++) {
            uint32_t ad = baseA + (wm * 32 + mi * 16 + (lane & 15)) * 112
                          + ks * 32 + (lane >> 4) * 16;
            ldsm_x4(ad, af[mi][0], af[mi][1], af[mi][2], af[mi][3]);
        }
#pragma unroll
        for (int np = 0; np < 2; np++) {
            uint32_t bd = baseB + (ks * 16 + (lane & 15)) * 144
                          + (wn * 32 + np * 16) * 2 + (lane >> 4) * 16;
            ldsm_x4_t(bd, bf[np][0], bf[np][1], bf[np][2], bf[np][3]);
        }
#pragma unroll
        for (int mi = 0; mi < 2; mi++) {
#pragma unroll
            for (int ni = 0; ni < 4; ni++) {
                mma16816(acc[mi][ni][0], acc[mi][ni][1], acc[mi][ni][2], acc[mi][ni][3],
                         af[mi][0], af[mi][1], af[mi][2], af[mi][3],
                         bf[ni >> 1][(ni & 1) * 2], bf[ni >> 1][(ni & 1) * 2 + 1]);
            }
        }
    }
}

__global__ __launch_bounds__(256) void k_gemm1(const float* __restrict__ x,
                                               const float* __restrict__ W) {
    __shared__ __align__(16) __half As[2][128][56];   // 112B row stride
    __shared__ __align__(16) __half Bs[2][32][72];    // 144B row stride
    const int bm = blockIdx.x * 128;
    const int tid = threadIdx.x;
    const int warp = tid >> 5, lane = tid & 31;
    const int wm = warp & 3, wn = warp >> 2;   // 4 x 2 warp grid

    int arow[4], akq[4], brow[2], bnc[2];
#pragma unroll
    for (int i = 0; i < 4; i++) { int f = tid * 4 + i; arow[i] = f >> 3; akq[i] = (f & 7) * 4; }
#pragma unroll
    for (int i = 0; i < 2; i++) { int f = tid * 2 + i; brow[i] = f >> 4; bnc[i] = (f & 15) * 4; }

    float4 ra[4], rb[2];
    float acc[2][4][4];
#pragma unroll
    for (int mi = 0; mi < 2; mi++)
#pragma unroll
        for (int ni = 0; ni < 4; ni++)
#pragma unroll
            for (int q = 0; q < 4; q++) acc[mi][ni][q] = 0.f;

    auto ldg = [&](int k0) {
#pragma unroll
        for (int i = 0; i < 4; i++)
            ra[i] = (bm + arow[i] < NN)
                ? *(const float4*)&x[(size_t)(bm + arow[i]) * FIN + k0 + akq[i]]
                : make_float4(0.f, 0.f, 0.f, 0.f);
#pragma unroll
        for (int i = 0; i < 2; i++)
            rb[i] = *(const float4*)&W[(size_t)(k0 + brow[i]) * 64 + bnc[i]];
    };
    auto sts = [&](int b) {
#pragma unroll
        for (int i = 0; i < 4; i++) {
            __half2* p = (__half2*)&As[b][arow[i]][akq[i]];
            p[0] = __floats2half2_rn(ra[i].x, ra[i].y);
            p[1] = __floats2half2_rn(ra[i].z, ra[i].w);
        }
#pragma unroll
        for (int i = 0; i < 2; i++) {
            __half2* p = (__half2*)&Bs[b][brow[i]][bnc[i]];
            p[0] = __floats2half2_rn(rb[i].x, rb[i].y);
            p[1] = __floats2half2_rn(rb[i].z, rb[i].w);
        }
    };

    ldg(0); sts(0); __syncthreads();
    int buf = 0;
    for (int ch = 1; ch < 16; ch++) {
        ldg(ch * 32);
        gemm1_compute((uint32_t)__cvta_generic_to_shared(&As[buf][0][0]),
                      (uint32_t)__cvta_generic_to_shared(&Bs[buf][0][0]),
                      wm, wn, lane, acc);
        sts(buf ^ 1);
        __syncthreads();
        buf ^= 1;
    }
    gemm1_compute((uint32_t)__cvta_generic_to_shared(&As[buf][0][0]),
                  (uint32_t)__cvta_generic_to_shared(&Bs[buf][0][0]),
                  wm, wn, lane, acc);

#pragma unroll
    for (int mi = 0; mi < 2; mi++) {
        int r0 = bm + wm * 32 + mi * 16 + (lane >> 2);
#pragma unroll
        for (int ni = 0; ni < 4; ni++) {
            int cc = wn * 32 + ni * 8 + (lane & 3) * 2;
            if (r0 < NN)
                *(__half2*)&g_h1[(size_t)r0 * 64 + cc] =
                    __floats2half2_rn(acc[mi][ni][0], acc[mi][ni][1]);
            if (r0 + 8 < NN)
                *(__half2*)&g_h1[(size_t)(r0 + 8) * 64 + cc] =
                    __floats2half2_rn(acc[mi][ni][2], acc[mi][ni][3]);
        }
    }
}

// ---------------- GEMM2: h2 = hid @ W2 (fp16 out) ----------------------------
__global__ __launch_bounds__(256) void k_gemm2(const float* __restrict__ W) {
    __shared__ float As[64][68];
    __shared__ float Bs[64][80];
    const int bm = blockIdx.x * 64;
    const int tid = threadIdx.x;
    const int tx = tid & 15, ty = tid >> 4;
    for (int i = tid; i < 64 * 80; i += 256) Bs[i / 80][i % 80] = W[i];
    const int ar = tid >> 4, ac = (tid & 15) * 4;
#pragma unroll
    for (int rr = 0; rr < 4; rr++) {
        int row = ar + rr * 16;
        float4 v = make_float4(0.f, 0.f, 0.f, 0.f);
        if (bm + row < NN)
            v = *(const float4*)&g_hid[(size_t)(bm + row) * 64 + ac];
        As[ac + 0][row] = v.x; As[ac + 1][row] = v.y;
        As[ac + 2][row] = v.z; As[ac + 3][row] = v.w;
    }
    __syncthreads();
    float acc[4][5] = {};
#pragma unroll 8
    for (int k = 0; k < 64; k++) {
        float4 a4 = *(const float4*)&As[k][ty * 4];
        float av[4] = {a4.x, a4.y, a4.z, a4.w};
        float bv[5];
#pragma unroll
        for (int j = 0; j < 5; j++) bv[j] = Bs[k][tx * 5 + j];
#pragma unroll
        for (int i = 0; i < 4; i++)
#pragma unroll
            for (int j = 0; j < 5; j++) acc[i][j] += av[i] * bv[j];
    }
#pragma unroll
    for (int i = 0; i < 4; i++) {
        int row = bm + ty * 4 + i;
        if (row < NN) {
#pragma unroll
            for (int j = 0; j < 5; j++)
                g_h2[(size_t)row * 80 + tx * 5 + j] = __float2half_rn(acc[i][j]);
        }
    }
}

// ---------------- attention scores + per-head global max of s_src ------------
__device__ __forceinline__ void calcs_body(const __half* __restrict__ h,
                                           const float* __restrict__ asrc,
                                           const float* __restrict__ adst,
                                           float* __restrict__ ss,
                                           float* __restrict__ sd,
                                           float* __restrict__ Ms,
                                           int C, int D) {
    __shared__ float red[8][9];
    int i = blockIdx.x * blockDim.x + threadIdx.x;
    int node = i >> 3, hh = i & 7;
    float a = -INFINITY, b = 0.f;
    if (i < NN * HH) {
        const __half2* hp = (const __half2*)(h + (size_t)node * D + hh * C);
        a = 0.f;
        for (int c = 0; c < C / 2; c++) {
            float2 v = __half22float2(hp[c]);
            a += v.x * asrc[hh * C + 2 * c] + v.y * asrc[hh * C + 2 * c + 1];
            b += v.x * adst[hh * C + 2 * c] + v.y * adst[hh * C + 2 * c + 1];
        }
        ss[i] = a; sd[i] = b;
    }
    float mx = a;
    mx = fmaxf(mx, __shfl_xor_sync(0xFFFFFFFFu, mx, 8));
    mx = fmaxf(mx, __shfl_xor_sync(0xFFFFFFFFu, mx, 16));
    int warp = threadIdx.x >> 5, lane = threadIdx.x & 31;
    if (lane < 8) red[warp][lane] = mx;
    __syncthreads();
    if (warp == 0) {
        float v = red[lane & 7][0];
#pragma unroll
        for (int w = 1; w < 8; w++) v = fmaxf(v, red[lane & 7][w]);
        if (lane < 8) atomicMaxF(&Ms[lane], v);
    }
}
__global__ void k_calcs1(const float* __restrict__ as, const float* __restrict__ ad) {
    calcs_body(g_h1, as, ad, g_ss1, g_sd1, &g_Ms[0], C1, D1);
}
__global__ void k_calcs2(const float* __restrict__ as, const float* __restrict__ ad) {
    calcs_body(g_h2, as, ad, g_ss2, g_sd2, &g_Ms[8], C2, D2);
}

// ---------------- fused GAT layer 1: warp/dst, fp16 gather, 4 edges/iter -----
__global__ __launch_bounds__(256) void k_gat1(const float* __restrict__ b1) {
    __shared__ int   s_src[8][32];
    __shared__ float s_ex[8][32][8];
    int w = threadIdx.x >> 5, lane = threadIdx.x & 31;
    int dst = blockIdx.x * 8 + w;
    if (dst >= NN) return;
    int off = g_off[dst], deg = g_deg[dst];
    float sdv[8], mb[8];
    {
        float4 t0 = *(const float4*)&g_sd1[(size_t)dst * 8];
        float4 t1 = *(const float4*)&g_sd1[(size_t)dst * 8 + 4];
        sdv[0]=t0.x; sdv[1]=t0.y; sdv[2]=t0.z; sdv[3]=t0.w;
        sdv[4]=t1.x; sdv[5]=t1.y; sdv[6]=t1.z; sdv[7]=t1.w;
#pragma unroll
        for (int h = 0; h < 8; h++) mb[h] = lrelu(__ldg(&g_Ms[h]) + sdv[h]);
    }
    float dn[8] = {0,0,0,0,0,0,0,0};
    float acc[8] = {0,0,0,0,0,0,0,0};
    const int c = lane & 7;
    const int eidx = lane >> 3;
    for (int t = 0; t < deg; t += 32) {
        int j = t + lane;
        if (j < deg) {
            int src = g_csrc[off + j];
            s_src[w][lane] = src;
            float4 a0 = *(const float4*)&g_ss1[(size_t)src * 8];
            float4 a1 = *(const float4*)&g_ss1[(size_t)src * 8 + 4];
            float sv[8] = {a0.x, a0.y, a0.z, a0.w, a1.x, a1.y, a1.z, a1.w};
#pragma unroll
            for (int h = 0; h < 8; h++) {
                float ex = expf(lrelu(sv[h] + sdv[h]) - mb[h]);
                dn[h] += ex;
                s_ex[w][lane][h] = ex;
            }
        }
        __syncwarp();
        int cnt = min(32, deg - t);
        for (int jj = 0; jj < cnt; jj += 4) {
            int je = jj + eidx;
            if (je < cnt) {
                int src = s_src[w][je];
                uint4 u = *(const uint4*)&g_h1[(size_t)src * 64 + c * 8];
                float ex = s_ex[w][je][c];
                const __half2* hp = (const __half2*)&u;
#pragma unroll
                for (int q = 0; q < 4; q++) {
                    float2 f = __half22float2(hp[q]);
                    acc[2 * q]     += f.x * ex;
                    acc[2 * q + 1] += f.y * ex;
                }
            }
        }
        __syncwarp();
    }
#pragma unroll
    for (int k = 0; k < 8; k++) {
        acc[k] += __shfl_xor_sync(0xFFFFFFFFu, acc[k], 8);
        acc[k] += __shfl_xor_sync(0xFFFFFFFFu, acc[k], 16);
    }
#pragma unroll
    for (int h = 0; h < 8; h++)
#pragma unroll
        for (int o = 16; o; o >>= 1) dn[h] += __shfl_xor_sync(0xFFFFFFFFu, dn[h], o);
    if (lane < 8) {
        float inv = 1.f / fmaxf(dn[lane], 1e-35f);
        float v[8];
#pragma unroll
        for (int k = 0; k < 8; k++) {
            v[k] = acc[k] * inv + b1[lane * 8 + k];
            v[k] = v[k] > 0.f ? v[k] : (expf(v[k]) - 1.f);
        }
        float4* p = (float4*)&g_hid[(size_t)dst * 64 + lane * 8];
        p[0] = make_float4(v[0], v[1], v[2], v[3]);
        p[1] = make_float4(v[4], v[5], v[6], v[7]);
    }
}

// ---------------- fused GAT layer 2 + log_softmax: fp16 gather, 3 edges/iter -
__global__ __launch_bounds__(256) void k_gat2(const float* __restrict__ b2,
                                              float* __restrict__ out) {
    __shared__ int   s_src[8][32];
    __shared__ float s_ex[8][32][8];
    int w = threadIdx.x >> 5, lane = threadIdx.x & 31;
    int dst = blockIdx.x * 8 + w;
    if (dst >= NN) return;
    int off = g_off[dst], deg = g_deg[dst];
    float sdv[8], mb[8];
    {
        float4 t0 = *(const float4*)&g_sd2[(size_t)dst * 8];
        float4 t1 = *(const float4*)&g_sd2[(size_t)dst * 8 + 4];
        sdv[0]=t0.x; sdv[1]=t0.y; sdv[2]=t0.z; sdv[3]=t0.w;
        sdv[4]=t1.x; sdv[5]=t1.y; sdv[6]=t1.z; sdv[7]=t1.w;
#pragma unroll
        for (int h = 0; h < 8; h++) mb[h] = lrelu(__ldg(&g_Ms[8 + h]) + sdv[h]);
    }
    float dn[8] = {0,0,0,0,0,0,0,0};
    float acc[8] = {0,0,0,0,0,0,0,0};
    const int eidx = lane / 10;
    const int c = lane - eidx * 10;
    const bool gactive = lane < 30;
    int hk[8];
#pragma unroll
    for (int k = 0; k < 8; k++) hk[k] = (c * 8 + k) / 10;
    for (int t = 0; t < deg; t += 32) {
        int j = t + lane;
        if (j < deg) {
            int src = g_csrc[off + j];
            s_src[w][lane] = src;
            float4 a0 = *(const float4*)&g_ss2[(size_t)src * 8];
            float4 a1 = *(const float4*)&g_ss2[(size_t)src * 8 + 4];
            float sv[8] = {a0.x, a0.y, a0.z, a0.w, a1.x, a1.y, a1.z, a1.w};
#pragma unroll
            for (int h = 0; h < 8; h++) {
                float ex = expf(lrelu(sv[h] + sdv[h]) - mb[h]);
                dn[h] += ex;
                s_ex[w][lane][h] = ex;
            }
        }
        __syncwarp();
        int cnt = min(32, deg - t);
        for (int jj = 0; jj < cnt; jj += 3) {
            int je = jj + eidx;
            if (gactive && je < cnt) {
                int src = s_src[w][je];
                uint4 u = *(const uint4*)&g_h2[(size_t)src * 80 + c * 8];
                const __half2* hp = (const __half2*)&u;
#pragma unroll
                for (int q = 0; q < 4; q++) {
                    float2 f = __half22float2(hp[q]);
                    acc[2 * q]     += f.x * s_ex[w][je][hk[2 * q]];
                    acc[2 * q + 1] += f.y * s_ex[w][je][hk[2 * q + 1]];
                }
            }
        }
        __syncwarp();
    }
#pragma unroll
    for (int k = 0; k < 8; k++) {
        float v10 = __shfl_sync(0xFFFFFFFFu, acc[k], (lane + 10) & 31);
        float v20 = __shfl_sync(0xFFFFFFFFu, acc[k], (lane + 20) & 31);
        if (lane < 10) acc[k] += v10 + v20;
    }
#pragma unroll
    for (int h = 0; h < 8; h++)
#pragma unroll
        for (int o = 16; o; o >>= 1) dn[h] += __shfl_xor_sync(0xFFFFFFFFu, dn[h], o);
    bool valid = lane < 10;
    float v[8];
    float lm = -INFINITY;
    if (valid) {
#pragma unroll
        for (int k = 0; k < 8; k++) {
            float inv = 1.f / fmaxf(dn[hk[k]], 1e-35f);
            v[k] = acc[k] * inv + b2[c * 8 + k];
            lm = fmaxf(lm, v[k]);
        }
    }
#pragma unroll
    for (int o = 16; o; o >>= 1) lm = fmaxf(lm, __shfl_xor_sync(0xFFFFFFFFu, lm, o));
    float se = 0.f;
    if (valid) {
#pragma unroll
        for (int k = 0; k < 8; k++) se += expf(v[k] - lm);
    }
#pragma unroll
    for (int o = 16; o; o >>= 1) se += __shfl_xor_sync(0xFFFFFFFFu, se, o);
    float lse = lm + logf(se);
    if (valid) {
        float4* p = (float4*)&out[(size_t)dst * 80 + c * 8];
        p[0] = make_float4(v[0] - lse, v[1] - lse, v[2] - lse, v[3] - lse);
        p[1] = make_float4(v[4] - lse, v[5] - lse, v[6] - lse, v[7] - lse);
    }
}

// ---------------- launcher ----------------------------------------------------
extern "C" void kernel_launch(void* const* d_in, const int* in_sizes, int n_in,
                              void* d_out, int out_size) {
    const float* x       = (const float*)d_in[0];
    const int*   ei      = (const int*)d_in[1];
    const float* W1      = (const float*)d_in[2];
    const float* as1     = (const float*)d_in[3];
    const float* ad1     = (const float*)d_in[4];
    const float* b1      = (const float*)d_in[5];
    const float* W2      = (const float*)d_in[6];
    const float* as2     = (const float*)d_in[7];
    const float* ad2     = (const float*)d_in[8];
    const float* b2      = (const float*)d_in[9];
    float* out           = (float*)d_out;

    const int E  = in_sizes[1] / 2;
    const int ET = E + NN;
    const int T = 256;
    const int NB = (NN + 1023) / 1024;

    k_zero<<<(NN + T - 1) / T, T>>>();
    k_hist<<<(ET + T - 1) / T, T>>>(ei, E, ET);
    k_scanA<<<NB, 1024>>>();
    k_scanB<<<1, 128>>>(NB);
    k_scanC<<<NB, 1024>>>();
    k_scatter<<<(ET + T - 1) / T, T>>>(ei, E, ET);

    k_gemm1<<<(NN + 127) / 128, 256>>>(x, W1);
    k_calcs1<<<(NN * HH + T - 1) / T, T>>>(as1, ad1);
    k_gat1<<<(NN + 7) / 8, 256>>>(b1);

    k_gemm2<<<(NN + 63) / 64, 256>>>(W2);
    k_calcs2<<<(NN * HH + T - 1) / T, T>>>(as2, ad2);
    k_gat2<<<(NN + 7) / 8, 256>>>(b2, out);
}

// round 13
// speedup vs baseline: 3.8862x; 1.0513x over previous
#include <cuda_runtime.h>
#include <cuda_fp16.h>
#include <stdint.h>
#include <math.h>

#define NN 100000
#define FIN 512
#define HH 8
#define D1 64
#define C1 8
#define D2 80
#define C2 10
#define MAXET 3300000   // E=3.2M + N self loops

// ---------------- scratch (device globals; no allocation allowed) ----------
__device__ __half g_h1[(size_t)NN * D1];
__device__ float  g_ss1[NN * HH];
__device__ float  g_sd1[NN * HH];
__device__ __half g_hid[(size_t)NN * D1];
__device__ __half g_h2[(size_t)NN * D2];
__device__ float  g_ss2[NN * HH];
__device__ float  g_sd2[NN * HH];
__device__ float  g_Ms[16];
__device__ int    g_deg[NN];
__device__ int    g_off[NN];
__device__ int    g_cur[NN];
__device__ int    g_bt[128];
__device__ int    g_csrc[MAXET];

// ---------------- helpers ---------------------------------------------------
__device__ __forceinline__ void atomicMaxF(float* a, float v) {
    if (v >= 0.f) atomicMax((int*)a, __float_as_int(v));
    else          atomicMin((unsigned int*)a, __float_as_uint(v));
}
__device__ __forceinline__ float lrelu(float t) { return t > 0.f ? t : 0.2f * t; }

// ---- mma plumbing: plain functions, scalar refs (nvcc-safe asm) --------------
__device__ __forceinline__ void ldsm_x4(uint32_t addr, uint32_t& r0, uint32_t& r1,
                                        uint32_t& r2, uint32_t& r3) {
    asm volatile("ldmatrix.sync.aligned.m8n8.x4.shared.b16 {%0,%1,%2,%3}, [%4];"
                 : "=r"(r0), "=r"(r1), "=r"(r2), "=r"(r3) : "r"(addr));
}
__device__ __forceinline__ void ldsm_x4_t(uint32_t addr, uint32_t& r0, uint32_t& r1,
                                          uint32_t& r2, uint32_t& r3) {
    asm volatile("ldmatrix.sync.aligned.m8n8.x4.trans.shared.b16 {%0,%1,%2,%3}, [%4];"
                 : "=r"(r0), "=r"(r1), "=r"(r2), "=r"(r3) : "r"(addr));
}
__device__ __forceinline__ void mma16816(float& d0, float& d1, float& d2, float& d3,
                                         uint32_t a0, uint32_t a1, uint32_t a2, uint32_t a3,
                                         uint32_t b0, uint32_t b1) {
    asm volatile("mma.sync.aligned.m16n8k16.row.col.f32.f16.f16.f32 "
                 "{%0,%1,%2,%3}, {%4,%5,%6,%7}, {%8,%9}, {%0,%1,%2,%3};"
                 : "+f"(d0), "+f"(d1), "+f"(d2), "+f"(d3)
                 : "r"(a0), "r"(a1), "r"(a2), "r"(a3), "r"(b0), "r"(b1));
}

// ---------------- CSR build ---------------------------------------------------
__global__ void k_zero() {
    int i = blockIdx.x * blockDim.x + threadIdx.x;
    if (i < NN) g_deg[i] = 0;
    if (i < 16) g_Ms[i] = -INFINITY;
}
__global__ void k_hist(const int* __restrict__ ei, int E, int ET) {
    int e = blockIdx.x * blockDim.x + threadIdx.x;
    if (e >= ET) return;
    int dst = (e < E) ? ei[(size_t)E + e] : (e - E);
    atomicAdd(&g_deg[dst], 1);
}
__global__ __launch_bounds__(1024) void k_scanA() {
    __shared__ int ws[32];
    int tid = threadIdx.x, lane = tid & 31, warp = tid >> 5;
    int i = blockIdx.x * 1024 + tid;
    int v = (i < NN) ? g_deg[i] : 0;
    int x = v;
#pragma unroll
    for (int o = 1; o < 32; o <<= 1) {
        int t = __shfl_up_sync(0xFFFFFFFFu, x, o);
        if (lane >= o) x += t;
    }
    if (lane == 31) ws[warp] = x;
    __syncthreads();
    if (warp == 0) {
        int y = ws[lane];
#pragma unroll
        for (int o = 1; o < 32; o <<= 1) {
            int t = __shfl_up_sync(0xFFFFFFFFu, y, o);
            if (lane >= o) y += t;
        }
        ws[lane] = y;
    }
    __syncthreads();
    int base = warp ? ws[warp - 1] : 0;
    int incl = base + x;
    if (i < NN) g_off[i] = incl - v;
    if (tid == 1023) g_bt[blockIdx.x] = incl;
}
__global__ __launch_bounds__(128) void k_scanB(int nb) {
    __shared__ int sh[128];
    int tid = threadIdx.x;
    int v = (tid < nb) ? g_bt[tid] : 0;
    sh[tid] = v;
    __syncthreads();
#pragma unroll
    for (int o = 1; o < 128; o <<= 1) {
        int t = (tid >= o) ? sh[tid - o] : 0;
        __syncthreads();
        sh[tid] += t;
        __syncthreads();
    }
    if (tid < nb) g_bt[tid] = sh[tid] - v;
}
__global__ __launch_bounds__(1024) void k_scanC() {
    int i = blockIdx.x * 1024 + threadIdx.x;
    if (i < NN) {
        int o = g_off[i] + g_bt[blockIdx.x];
        g_off[i] = o;
        g_cur[i] = o;
    }
}
__global__ void k_scatter(const int* __restrict__ ei, int E, int ET) {
    int e = blockIdx.x * blockDim.x + threadIdx.x;
    if (e >= ET) return;
    int src, dst;
    if (e < E) { src = ei[e]; dst = ei[(size_t)E + e]; }
    else       { src = dst = e - E; }
    int pos = atomicAdd(&g_cur[dst], 1);
    g_csrc[pos] = src;
}

// ------- GEMM1: h1 = x @ W1 via mma.sync m16n8k16 fp16 (fp32 accum) ----------
__device__ __forceinline__ void gemm1_compute(uint32_t baseA, uint32_t baseB,
                                              int wm, int wn, int lane,
                                              float (&acc)[2][4][4]) {
#pragma unroll
    for (int ks = 0; ks < 2; ks++) {
        uint32_t af[2][4], bf[2][4];
#pragma unroll
        for (int mi = 0; mi < 2; mi++) {
            uint32_t ad = baseA + (wm * 32 + mi * 16 + (lane & 15)) * 112
                          + ks * 32 + (lane >> 4) * 16;
            ldsm_x4(ad, af[mi][0], af[mi][1], af[mi][2], af[mi][3]);
        }
#pragma unroll
        for (int np = 0; np < 2; np++) {
            uint32_t bd = baseB + (ks * 16 + (lane & 15)) * 144
                          + (wn * 32 + np * 16) * 2 + (lane >> 4) * 16;
            ldsm_x4_t(bd, bf[np][0], bf[np][1], bf[np][2], bf[np][3]);
        }
#pragma unroll
        for (int mi = 0; mi < 2; mi++) {
#pragma unroll
            for (int ni = 0; ni < 4; ni++) {
                mma16816(acc[mi][ni][0], acc[mi][ni][1], acc[mi][ni][2], acc[mi][ni][3],
                         af[mi][0], af[mi][1], af[mi][2], af[mi][3],
                         bf[ni >> 1][(ni & 1) * 2], bf[ni >> 1][(ni & 1) * 2 + 1]);
            }
        }
    }
}

__global__ __launch_bounds__(256) void k_gemm1(const float* __restrict__ x,
                                               const float* __restrict__ W) {
    __shared__ __align__(16) __half As[2][128][56];   // 112B row stride
    __shared__ __align__(16) __half Bs[2][32][72];    // 144B row stride
    const int bm = blockIdx.x * 128;
    const int tid = threadIdx.x;
    const int warp = tid >> 5, lane = tid & 31;
    const int wm = warp & 3, wn = warp >> 2;   // 4 x 2 warp grid

    int arow[4], akq[4], brow[2], bnc[2];
#pragma unroll
    for (int i = 0; i < 4; i++) { int f = tid * 4 + i; arow[i] = f >> 3; akq[i] = (f & 7) * 4; }
#pragma unroll
    for (int i = 0; i < 2; i++) { int f = tid * 2 + i; brow[i] = f >> 4; bnc[i] = (f & 15) * 4; }

    float4 ra[4], rb[2];
    float acc[2][4][4];
#pragma unroll
    for (int mi = 0; mi < 2; mi++)
#pragma unroll
        for (int ni = 0; ni < 4; ni++)
#pragma unroll
            for (int q = 0; q < 4; q++) acc[mi][ni][q] = 0.f;

    auto ldg = [&](int k0) {
#pragma unroll
        for (int i = 0; i < 4; i++)
            ra[i] = (bm + arow[i] < NN)
                ? *(const float4*)&x[(size_t)(bm + arow[i]) * FIN + k0 + akq[i]]
                : make_float4(0.f, 0.f, 0.f, 0.f);
#pragma unroll
        for (int i = 0; i < 2; i++)
            rb[i] = *(const float4*)&W[(size_t)(k0 + brow[i]) * 64 + bnc[i]];
    };
    auto sts = [&](int b) {
#pragma unroll
        for (int i = 0; i < 4; i++) {
            __half2* p = (__half2*)&As[b][arow[i]][akq[i]];
            p[0] = __floats2half2_rn(ra[i].x, ra[i].y);
            p[1] = __floats2half2_rn(ra[i].z, ra[i].w);
        }
#pragma unroll
        for (int i = 0; i < 2; i++) {
            __half2* p = (__half2*)&Bs[b][brow[i]][bnc[i]];
            p[0] = __floats2half2_rn(rb[i].x, rb[i].y);
            p[1] = __floats2half2_rn(rb[i].z, rb[i].w);
        }
    };

    ldg(0); sts(0); __syncthreads();
    int buf = 0;
    for (int ch = 1; ch < 16; ch++) {
        ldg(ch * 32);
        gemm1_compute((uint32_t)__cvta_generic_to_shared(&As[buf][0][0]),
                      (uint32_t)__cvta_generic_to_shared(&Bs[buf][0][0]),
                      wm, wn, lane, acc);
        sts(buf ^ 1);
        __syncthreads();
        buf ^= 1;
    }
    gemm1_compute((uint32_t)__cvta_generic_to_shared(&As[buf][0][0]),
                  (uint32_t)__cvta_generic_to_shared(&Bs[buf][0][0]),
                  wm, wn, lane, acc);

#pragma unroll
    for (int mi = 0; mi < 2; mi++) {
        int r0 = bm + wm * 32 + mi * 16 + (lane >> 2);
#pragma unroll
        for (int ni = 0; ni < 4; ni++) {
            int cc = wn * 32 + ni * 8 + (lane & 3) * 2;
            if (r0 < NN)
                *(__half2*)&g_h1[(size_t)r0 * 64 + cc] =
                    __floats2half2_rn(acc[mi][ni][0], acc[mi][ni][1]);
            if (r0 + 8 < NN)
                *(__half2*)&g_h1[(size_t)(r0 + 8) * 64 + cc] =
                    __floats2half2_rn(acc[mi][ni][2], acc[mi][ni][3]);
        }
    }
}

// ------- GEMM2: h2 = hid(fp16) @ W2 via mma.sync, one-shot smem (K=64) -------
__global__ __launch_bounds__(256) void k_gemm2(const float* __restrict__ W) {
    __shared__ __align__(16) __half As[128][72];   // 144B row stride
    __shared__ __align__(16) __half Bs[64][88];    // 176B row stride
    const int bm = blockIdx.x * 128;
    const int tid = threadIdx.x;
    const int warp = tid >> 5, lane = tid & 31;

    // load A (hid fp16): 128 rows x 64 halves = 1024 chunks of 8 halves
#pragma unroll
    for (int i = 0; i < 4; i++) {
        int f = tid * 4 + i;
        int row = f >> 3, cc = (f & 7) * 8;
        uint4 v = make_uint4(0u, 0u, 0u, 0u);
        if (bm + row < NN) v = *(const uint4*)&g_hid[(size_t)(bm + row) * 64 + cc];
        *(uint4*)&As[row][cc] = v;
    }
    // load B: 64 x 80 fp32 -> fp16; 1280 float4 chunks
#pragma unroll
    for (int i = 0; i < 5; i++) {
        int f = tid * 5 + i;
        int row = f / 20, c4 = (f % 20) * 4;
        float4 v = *(const float4*)&W[(size_t)row * 80 + c4];
        __half2* p = (__half2*)&Bs[row][c4];
        p[0] = __floats2half2_rn(v.x, v.y);
        p[1] = __floats2half2_rn(v.z, v.w);
    }
    __syncthreads();

    float acc[10][4];
#pragma unroll
    for (int ni = 0; ni < 10; ni++)
#pragma unroll
        for (int q = 0; q < 4; q++) acc[ni][q] = 0.f;

    uint32_t baseA = (uint32_t)__cvta_generic_to_shared(&As[0][0]);
    uint32_t baseB = (uint32_t)__cvta_generic_to_shared(&Bs[0][0]);
#pragma unroll
    for (int ks = 0; ks < 4; ks++) {
        uint32_t a0, a1, a2, a3;
        uint32_t ad = baseA + (warp * 16 + (lane & 15)) * 144 + ks * 32 + (lane >> 4) * 16;
        ldsm_x4(ad, a0, a1, a2, a3);
#pragma unroll
        for (int nt = 0; nt < 5; nt++) {
            uint32_t b0, b1, b2, b3;
            uint32_t bd = baseB + (ks * 16 + (lane & 15)) * 176 + nt * 32 + (lane >> 4) * 16;
            ldsm_x4_t(bd, b0, b1, b2, b3);
            mma16816(acc[nt * 2][0], acc[nt * 2][1], acc[nt * 2][2], acc[nt * 2][3],
                     a0, a1, a2, a3, b0, b1);
            mma16816(acc[nt * 2 + 1][0], acc[nt * 2 + 1][1], acc[nt * 2 + 1][2], acc[nt * 2 + 1][3],
                     a0, a1, a2, a3, b2, b3);
        }
    }

    int r0 = bm + warp * 16 + (lane >> 2);
#pragma unroll
    for (int ni = 0; ni < 10; ni++) {
        int cc = ni * 8 + (lane & 3) * 2;
        if (r0 < NN)
            *(__half2*)&g_h2[(size_t)r0 * 80 + cc] = __floats2half2_rn(acc[ni][0], acc[ni][1]);
        if (r0 + 8 < NN)
            *(__half2*)&g_h2[(size_t)(r0 + 8) * 80 + cc] = __floats2half2_rn(acc[ni][2], acc[ni][3]);
    }
}

// ---------------- attention scores + per-head global max of s_src ------------
__device__ __forceinline__ void calcs_body(const __half* __restrict__ h,
                                           const float* __restrict__ asrc,
                                           const float* __restrict__ adst,
                                           float* __restrict__ ss,
                                           float* __restrict__ sd,
                                           float* __restrict__ Ms,
                                           int C, int D) {
    __shared__ float red[8][9];
    int i = blockIdx.x * blockDim.x + threadIdx.x;
    int node = i >> 3, hh = i & 7;
    float a = -INFINITY, b = 0.f;
    if (i < NN * HH) {
        const __half2* hp = (const __half2*)(h + (size_t)node * D + hh * C);
        a = 0.f;
        for (int c = 0; c < C / 2; c++) {
            float2 v = __half22float2(hp[c]);
            a += v.x * asrc[hh * C + 2 * c] + v.y * asrc[hh * C + 2 * c + 1];
            b += v.x * adst[hh * C + 2 * c] + v.y * adst[hh * C + 2 * c + 1];
        }
        ss[i] = a; sd[i] = b;
    }
    float mx = a;
    mx = fmaxf(mx, __shfl_xor_sync(0xFFFFFFFFu, mx, 8));
    mx = fmaxf(mx, __shfl_xor_sync(0xFFFFFFFFu, mx, 16));
    int warp = threadIdx.x >> 5, lane = threadIdx.x & 31;
    if (lane < 8) red[warp][lane] = mx;
    __syncthreads();
    if (warp == 0) {
        float v = red[lane & 7][0];
#pragma unroll
        for (int w = 1; w < 8; w++) v = fmaxf(v, red[lane & 7][w]);
        if (lane < 8) atomicMaxF(&Ms[lane], v);
    }
}
__global__ void k_calcs1(const float* __restrict__ as, const float* __restrict__ ad) {
    calcs_body(g_h1, as, ad, g_ss1, g_sd1, &g_Ms[0], C1, D1);
}
__global__ void k_calcs2(const float* __restrict__ as, const float* __restrict__ ad) {
    calcs_body(g_h2, as, ad, g_ss2, g_sd2, &g_Ms[8], C2, D2);
}

// ---------------- fused GAT layer 1: warp/dst, fp16 gather, 4 edges/iter -----
__global__ __launch_bounds__(256) void k_gat1(const float* __restrict__ b1) {
    __shared__ int   s_src[8][32];
    __shared__ float s_ex[8][32][8];
    int w = threadIdx.x >> 5, lane = threadIdx.x & 31;
    int dst = blockIdx.x * 8 + w;
    if (dst >= NN) return;
    int off = g_off[dst], deg = g_deg[dst];
    float sdv[8], mb[8];
    {
        float4 t0 = *(const float4*)&g_sd1[(size_t)dst * 8];
        float4 t1 = *(const float4*)&g_sd1[(size_t)dst * 8 + 4];
        sdv[0]=t0.x; sdv[1]=t0.y; sdv[2]=t0.z; sdv[3]=t0.w;
        sdv[4]=t1.x; sdv[5]=t1.y; sdv[6]=t1.z; sdv[7]=t1.w;
#pragma unroll
        for (int h = 0; h < 8; h++) mb[h] = lrelu(__ldg(&g_Ms[h]) + sdv[h]);
    }
    float dn[8] = {0,0,0,0,0,0,0,0};
    float acc[8] = {0,0,0,0,0,0,0,0};
    const int c = lane & 7;
    const int eidx = lane >> 3;
    for (int t = 0; t < deg; t += 32) {
        int j = t + lane;
        if (j < deg) {
            int src = g_csrc[off + j];
            s_src[w][lane] = src;
            float4 a0 = *(const float4*)&g_ss1[(size_t)src * 8];
            float4 a1 = *(const float4*)&g_ss1[(size_t)src * 8 + 4];
            float sv[8] = {a0.x, a0.y, a0.z, a0.w, a1.x, a1.y, a1.z, a1.w};
#pragma unroll
            for (int h = 0; h < 8; h++) {
                float ex = expf(lrelu(sv[h] + sdv[h]) - mb[h]);
                dn[h] += ex;
                s_ex[w][lane][h] = ex;
            }
        }
        __syncwarp();
        int cnt = min(32, deg - t);
        for (int jj = 0; jj < cnt; jj += 4) {
            int je = jj + eidx;
            if (je < cnt) {
                int src = s_src[w][je];
                uint4 u = *(const uint4*)&g_h1[(size_t)src * 64 + c * 8];
                float ex = s_ex[w][je][c];
                const __half2* hp = (const __half2*)&u;
#pragma unroll
                for (int q = 0; q < 4; q++) {
                    float2 f = __half22float2(hp[q]);
                    acc[2 * q]     += f.x * ex;
                    acc[2 * q + 1] += f.y * ex;
                }
            }
        }
        __syncwarp();
    }
#pragma unroll
    for (int k = 0; k < 8; k++) {
        acc[k] += __shfl_xor_sync(0xFFFFFFFFu, acc[k], 8);
        acc[k] += __shfl_xor_sync(0xFFFFFFFFu, acc[k], 16);
    }
#pragma unroll
    for (int h = 0; h < 8; h++)
#pragma unroll
        for (int o = 16; o; o >>= 1) dn[h] += __shfl_xor_sync(0xFFFFFFFFu, dn[h], o);
    if (lane < 8) {
        float inv = 1.f / fmaxf(dn[lane], 1e-35f);
        float v[8];
#pragma unroll
        for (int k = 0; k < 8; k++) {
            v[k] = acc[k] * inv + b1[lane * 8 + k];
            v[k] = v[k] > 0.f ? v[k] : (expf(v[k]) - 1.f);
        }
        __half2 hh[4];
#pragma unroll
        for (int q = 0; q < 4; q++) hh[q] = __floats2half2_rn(v[2 * q], v[2 * q + 1]);
        *(uint4*)&g_hid[(size_t)dst * 64 + lane * 8] = *(uint4*)hh;
    }
}

// ---------------- fused GAT layer 2 + log_softmax: fp16 gather, 3 edges/iter -
__global__ __launch_bounds__(256) void k_gat2(const float* __restrict__ b2,
                                              float* __restrict__ out) {
    __shared__ int   s_src[8][32];
    __shared__ float s_ex[8][32][8];
    int w = threadIdx.x >> 5, lane = threadIdx.x & 31;
    int dst = blockIdx.x * 8 + w;
    if (dst >= NN) return;
    int off = g_off[dst], deg = g_deg[dst];
    float sdv[8], mb[8];
    {
        float4 t0 = *(const float4*)&g_sd2[(size_t)dst * 8];
        float4 t1 = *(const float4*)&g_sd2[(size_t)dst * 8 + 4];
        sdv[0]=t0.x; sdv[1]=t0.y; sdv[2]=t0.z; sdv[3]=t0.w;
        sdv[4]=t1.x; sdv[5]=t1.y; sdv[6]=t1.z; sdv[7]=t1.w;
#pragma unroll
        for (int h = 0; h < 8; h++) mb[h] = lrelu(__ldg(&g_Ms[8 + h]) + sdv[h]);
    }
    float dn[8] = {0,0,0,0,0,0,0,0};
    float acc[8] = {0,0,0,0,0,0,0,0};
    const int eidx = lane / 10;
    const int c = lane - eidx * 10;
    const bool gactive = lane < 30;
    int hk[8];
#pragma unroll
    for (int k = 0; k < 8; k++) hk[k] = (c * 8 + k) / 10;
    for (int t = 0; t < deg; t += 32) {
        int j = t + lane;
        if (j < deg) {
            int src = g_csrc[off + j];
            s_src[w][lane] = src;
            float4 a0 = *(const float4*)&g_ss2[(size_t)src * 8];
            float4 a1 = *(const float4*)&g_ss2[(size_t)src * 8 + 4];
            float sv[8] = {a0.x, a0.y, a0.z, a0.w, a1.x, a1.y, a1.z, a1.w};
#pragma unroll
            for (int h = 0; h < 8; h++) {
                float ex = expf(lrelu(sv[h] + sdv[h]) - mb[h]);
                dn[h] += ex;
                s_ex[w][lane][h] = ex;
            }
        }
        __syncwarp();
        int cnt = min(32, deg - t);
        for (int jj = 0; jj < cnt; jj += 3) {
            int je = jj + eidx;
            if (gactive && je < cnt) {
                int src = s_src[w][je];
                uint4 u = *(const uint4*)&g_h2[(size_t)src * 80 + c * 8];
                const __half2* hp = (const __half2*)&u;
#pragma unroll
                for (int q = 0; q < 4; q++) {
                    float2 f = __half22float2(hp[q]);
                    acc[2 * q]     += f.x * s_ex[w][je][hk[2 * q]];
                    acc[2 * q + 1] += f.y * s_ex[w][je][hk[2 * q + 1]];
                }
            }
        }
        __syncwarp();
    }
#pragma unroll
    for (int k = 0; k < 8; k++) {
        float v10 = __shfl_sync(0xFFFFFFFFu, acc[k], (lane + 10) & 31);
        float v20 = __shfl_sync(0xFFFFFFFFu, acc[k], (lane + 20) & 31);
        if (lane < 10) acc[k] += v10 + v20;
    }
#pragma unroll
    for (int h = 0; h < 8; h++)
#pragma unroll
        for (int o = 16; o; o >>= 1) dn[h] += __shfl_xor_sync(0xFFFFFFFFu, dn[h], o);
    bool valid = lane < 10;
    float v[8];
    float lm = -INFINITY;
    if (valid) {
#pragma unroll
        for (int k = 0; k < 8; k++) {
            float inv = 1.f / fmaxf(dn[hk[k]], 1e-35f);
            v[k] = acc[k] * inv + b2[c * 8 + k];
            lm = fmaxf(lm, v[k]);
        }
    }
#pragma unroll
    for (int o = 16; o; o >>= 1) lm = fmaxf(lm, __shfl_xor_sync(0xFFFFFFFFu, lm, o));
    float se = 0.f;
    if (valid) {
#pragma unroll
        for (int k = 0; k < 8; k++) se += expf(v[k] - lm);
    }
#pragma unroll
    for (int o = 16; o; o >>= 1) se += __shfl_xor_sync(0xFFFFFFFFu, se, o);
    float lse = lm + logf(se);
    if (valid) {
        float4* p = (float4*)&out[(size_t)dst * 80 + c * 8];
        p[0] = make_float4(v[0] - lse, v[1] - lse, v[2] - lse, v[3] - lse);
        p[1] = make_float4(v[4] - lse, v[5] - lse, v[6] - lse, v[7] - lse);
    }
}

// ---------------- launcher ----------------------------------------------------
extern "C" void kernel_launch(void* const* d_in, const int* in_sizes, int n_in,
                              void* d_out, int out_size) {
    const float* x       = (const float*)d_in[0];
    const int*   ei      = (const int*)d_in[1];
    const float* W1      = (const float*)d_in[2];
    const float* as1     = (const float*)d_in[3];
    const float* ad1     = (const float*)d_in[4];
    const float* b1      = (const float*)d_in[5];
    const float* W2      = (const float*)d_in[6];
    const float* as2     = (const float*)d_in[7];
    const float* ad2     = (const float*)d_in[8];
    const float* b2      = (const float*)d_in[9];
    float* out           = (float*)d_out;

    const int E  = in_sizes[1] / 2;
    const int ET = E + NN;
    const int T = 256;
    const int NB = (NN + 1023) / 1024;

    k_zero<<<(NN + T - 1) / T, T>>>();
    k_hist<<<(ET + T - 1) / T, T>>>(ei, E, ET);
    k_scanA<<<NB, 1024>>>();
    k_scanB<<<1, 128>>>(NB);
    k_scanC<<<NB, 1024>>>();
    k_scatter<<<(ET + T - 1) / T, T>>>(ei, E, ET);

    k_gemm1<<<(NN + 127) / 128, 256>>>(x, W1);
    k_calcs1<<<(NN * HH + T - 1) / T, T>>>(as1, ad1);
    k_gat1<<<(NN + 7) / 8, 256>>>(b1);

    k_gemm2<<<(NN + 127) / 128, 256>>>(W2);
    k_calcs2<<<(NN * HH + T - 1) / T, T>>>(as2, ad2);
    k_gat2<<<(NN + 7) / 8, 256>>>(b2, out);
}